// round 4
// baseline (speedup 1.0000x reference)
#include <cuda_runtime.h>
#include <math.h>

typedef unsigned long long ull;

#define NB 4096

// ---------------- device-global gate storage (pre-packed for f32x2) ----------------
// Packed entry for complex g: .x = (g.re, g.re), .y = (-g.im, g.im)
// acc(re,im) += g*v  ==  acc = fma2(.x, (v.re,v.im), acc); acc = fma2(.y, (v.im,v.re), acc)
__device__ ulonglong2 g_bs[48 * 4096];   // [L][2][6] 64x64, transposed: G[(j1*8+j2)*64 + ip]
__device__ ulonglong2 g_sq[16 * 64];     // [L][4] 8x8: G[i*8+j] = U[i][j]
__device__ ulonglong2 g_dp[16 * 64];     // [L][4] 8x8 (kerr folded): G[i*8+j]
__device__ float      g_enc0[NB * 4 * 8];// encode matrices, column 0 only (real)

__constant__ int c_pi[6] = {0,0,0,1,1,2};
__constant__ int c_pj[6] = {1,2,3,2,3,3};
__constant__ int c_oa[6] = {2,1,1,0,0,0};
__constant__ int c_ob[6] = {3,3,2,3,2,1};

// ---------------- packed helpers ----------------
__device__ __forceinline__ ull pk(float lo, float hi) {
    ull r; asm("mov.b64 %0,{%1,%2};" : "=l"(r) : "f"(lo), "f"(hi)); return r;
}
__device__ __forceinline__ void upk(ull v, float& lo, float& hi) {
    asm("mov.b64 {%0,%1},%2;" : "=f"(lo), "=f"(hi) : "l"(v));
}
__device__ __forceinline__ ull swp(ull v) {
    float lo, hi; upk(v, lo, hi); return pk(hi, lo);
}
__device__ __forceinline__ ull fma2(ull a, ull b, ull c) {
    ull r; asm("fma.rn.f32x2 %0,%1,%2,%3;" : "=l"(r) : "l"(a), "l"(b), "l"(c)); return r;
}
__device__ __forceinline__ ull lds64(unsigned addr) {
    ull r; asm volatile("ld.shared.b64 %0,[%1];" : "=l"(r) : "r"(addr)); return r;
}
__device__ __forceinline__ void sts64(unsigned addr, ull v) {
    asm volatile("st.shared.b64 [%0],%1;" :: "r"(addr), "l"(v));
}
__device__ __forceinline__ ulonglong2 pack2(float re, float im) {
    ulonglong2 r; r.x = pk(re, re); r.y = pk(-im, im); return r;
}

// ---------------- small expm (scaling-and-squaring Taylor) ----------------
__device__ void matmul_c(const float2* X, const float2* Y, float2* Z, int n, float scale) {
    for (int i = 0; i < n; i++)
        for (int j = 0; j < n; j++) {
            float ar = 0.f, ai = 0.f;
            for (int m = 0; m < n; m++) {
                float2 a = X[i*8+m], b = Y[m*8+j];
                ar += a.x*b.x - a.y*b.y;
                ai += a.x*b.y + a.y*b.x;
            }
            Z[i*8+j] = make_float2(ar*scale, ai*scale);
        }
}

__device__ void expm_c8(const float2* H, float2* E, int n) {
    float norm = 0.f;
    for (int i = 0; i < n; i++) {
        float r = 0.f;
        for (int j = 0; j < n; j++) r += fabsf(H[i*8+j].x) + fabsf(H[i*8+j].y);
        norm = fmaxf(norm, r);
    }
    int s = 0;
    while (norm > 0.5f && s < 30) { norm *= 0.5f; s++; }
    float sc = ldexpf(1.f, -s);
    float2 T[64], P[64], Q[64];
    for (int i = 0; i < n; i++)
        for (int j = 0; j < n; j++) {
            float2 h = H[i*8+j];
            float2 tv = make_float2(h.x*sc, h.y*sc);
            T[i*8+j] = tv; P[i*8+j] = tv; E[i*8+j] = tv;
        }
    for (int i = 0; i < n; i++) E[i*8+i].x += 1.f;
    for (int k = 2; k <= 16; k++) {
        matmul_c(P, T, Q, n, 1.f/(float)k);
        for (int i = 0; i < n; i++)
            for (int j = 0; j < n; j++) {
                P[i*8+j] = Q[i*8+j];
                E[i*8+j].x += Q[i*8+j].x;
                E[i*8+j].y += Q[i*8+j].y;
            }
    }
    for (int it = 0; it < s; it++) {
        matmul_c(E, E, Q, n, 1.f);
        for (int i = 0; i < n; i++)
            for (int j = 0; j < n; j++) E[i*8+j] = Q[i*8+j];
    }
}

__device__ void matmul_r(const float* X, const float* Y, float* Z, int n, float scale) {
    for (int i = 0; i < n; i++)
        for (int j = 0; j < n; j++) {
            float a = 0.f;
            for (int m = 0; m < n; m++) a += X[i*8+m] * Y[m*8+j];
            Z[i*8+j] = a * scale;
        }
}

__device__ void expm_r8(const float* H, float* E, int n) {
    float norm = 0.f;
    for (int i = 0; i < n; i++) {
        float r = 0.f;
        for (int j = 0; j < n; j++) r += fabsf(H[i*8+j]);
        norm = fmaxf(norm, r);
    }
    int s = 0;
    while (norm > 0.5f && s < 30) { norm *= 0.5f; s++; }
    float sc = ldexpf(1.f, -s);
    float T[64], P[64], Q[64];
    for (int i = 0; i < n; i++)
        for (int j = 0; j < n; j++) {
            float tv = H[i*8+j] * sc;
            T[i*8+j] = tv; P[i*8+j] = tv; E[i*8+j] = tv;
        }
    for (int i = 0; i < n; i++) E[i*8+i] += 1.f;
    for (int k = 2; k <= 16; k++) {
        matmul_r(P, T, Q, n, 1.f/(float)k);
        for (int i = 0; i < n; i++)
            for (int j = 0; j < n; j++) { P[i*8+j] = Q[i*8+j]; E[i*8+j] += Q[i*8+j]; }
    }
    for (int it = 0; it < s; it++) {
        matmul_r(E, E, Q, n, 1.f);
        for (int i = 0; i < n; i++)
            for (int j = 0; j < n; j++) E[i*8+j] = Q[i*8+j];
    }
}

// ---------------- precompute shared gates (with diagonal folding) ----------------
__global__ void precompute_kernel(
    const float* th1, const float* ph1, const float* th2, const float* ph2,
    const float* dr, const float* dph, const float* sr, const float* sph,
    const float* kerr)
{
    int tid = blockIdx.x * blockDim.x + threadIdx.x;
    if (tid < 720) {
        // beamsplitter: one photon-number block per thread (48 gates x 15 totals)
        int g  = tid / 15, tt = tid % 15;
        int l  = g / 12, k = (g / 6) % 2, p = g % 6;
        const float* TH = k ? th2 : th1;
        const float* PH = k ? ph2 : ph1;
        int mi = c_pi[p], mj = c_pj[p];
        float theta = TH[(l*4+mi)*4 + mj];
        float phi   = PH[(l*4+mi)*4 + mj];
        // folded diag phases: input-side (rot-pre, first touch per mode), output-side (rot-post)
        float a1 = 0.f, a2 = 0.f;
        if (p == 0) { a1 = PH[(l*4+0)*4 + 0]; a2 = PH[(l*4+1)*4 + 1]; }
        if (p == 1) { a2 = PH[(l*4+2)*4 + 2]; }
        if (p == 2) { a2 = PH[(l*4+3)*4 + 3]; }
        float b2 = PH[(l*4+mj)*4 + mi];
        int lo = tt > 7 ? tt - 7 : 0;
        int hi = tt < 7 ? tt : 7;
        int n  = hi - lo + 1;
        float2 H[64];
        for (int q = 0; q < 64; q++) H[q] = make_float2(0.f, 0.f);
        float cp = cosf(phi), sp = sinf(phi);
        for (int r = 0; r < n; r++) {
            int j1 = lo + r, j2 = tt - j1;
            if (r >= 1) {
                float mag = theta * sqrtf((float)(j1 * (j2 + 1)));
                H[(r-1)*8 + r] = make_float2(mag*cp, mag*sp);
            }
            if (r <= n - 2) {
                float mag = theta * sqrtf((float)((j1 + 1) * j2));
                H[(r+1)*8 + r] = make_float2(-mag*cp, mag*sp);
            }
        }
        float2 E[64];
        expm_c8(H, E, n);
        ulonglong2* dst = g_bs + g * 4096;
        for (int ir = 0; ir < n; ir++) {
            int i1 = lo + ir, i2 = tt - i1;
            int ipp = i1 * 8 + i2;
            for (int jr = 0; jr < n; jr++) {
                int j1 = lo + jr, j2 = tt - j1;
                int jpp = j1 * 8 + j2;
                float2 v = E[ir*8 + jr];
                float ang = b2 * (float)i2 + a1 * (float)j1 + a2 * (float)j2;
                float ca = cosf(ang), sa = sinf(ang);
                float vr = v.x*ca - v.y*sa;
                float vi = v.x*sa + v.y*ca;
                dst[jpp*64 + ipp] = pack2(vr, vi);
            }
        }
    } else if (tid < 736) {
        // squeeze
        int idx = tid - 720;
        float r = sr[idx], p = sph[idx];
        float2 H[64];
        for (int q = 0; q < 64; q++) H[q] = make_float2(0.f, 0.f);
        float cp = cosf(p), sp = sinf(p);
        for (int jj = 2; jj < 8; jj++) {
            float m = 0.5f * r * sqrtf((float)(jj * (jj - 1)));
            H[(jj-2)*8 + jj] = make_float2(m*cp, -m*sp);
            H[jj*8 + jj-2]   = make_float2(-m*cp, -m*sp);
        }
        float2 E[64];
        expm_c8(H, E, 8);
        ulonglong2* dst = g_sq + idx * 64;
        for (int i = 0; i < 8; i++)
            for (int j = 0; j < 8; j++)
                dst[i*8+j] = pack2(E[i*8+j].x, E[i*8+j].y);
    } else if (tid < 752) {
        // layer displacement with Kerr folded on output rows
        int idx = tid - 736;
        float r = dr[idx], p = dph[idx];
        float kp = kerr[idx];
        float amag = r * cosf(p);
        float aph  = r * sinf(p);
        float2 al = make_float2(amag * cosf(aph), amag * sinf(aph));
        float2 H[64];
        for (int q = 0; q < 64; q++) H[q] = make_float2(0.f, 0.f);
        for (int ii = 1; ii < 8; ii++) {
            float rt = sqrtf((float)ii);
            H[ii*8 + ii-1] = make_float2(al.x*rt, al.y*rt);
            H[(ii-1)*8 + ii] = make_float2(-al.x*rt, al.y*rt);
        }
        float2 E[64];
        expm_c8(H, E, 8);
        ulonglong2* dst = g_dp + idx * 64;
        for (int i = 0; i < 8; i++) {
            float ang = kp * (float)(i * i);
            float ca = cosf(ang), sa = sinf(ang);
            for (int j = 0; j < 8; j++) {
                float2 v = E[i*8+j];
                dst[i*8+j] = pack2(v.x*ca - v.y*sa, v.x*sa + v.y*ca);
            }
        }
    }
}

// ---------------- per-sample encoding displacement: only column 0 of expm ----------------
__global__ void encode_kernel(const float* x) {
    int tid = blockIdx.x * blockDim.x + threadIdx.x;
    if (tid >= NB * 4) return;
    float xv = x[tid];
    float H[64];
    for (int q = 0; q < 64; q++) H[q] = 0.f;
    for (int ii = 1; ii < 8; ii++) {
        float r = xv * sqrtf((float)ii);
        H[ii*8 + ii-1] = r;
        H[(ii-1)*8 + ii] = -r;
    }
    float E[64];
    expm_r8(H, E, 8);
    float* dst = g_enc0 + tid * 8;
    for (int i = 0; i < 8; i++) dst[i] = E[i*8 + 0];
}

// ---------------- main simulation (ping-pong smem, packed f32x2) ----------------
__device__ __forceinline__ void apply1(unsigned in, unsigned out,
                                       const ulonglong2* __restrict__ G, int m, int t) {
    int sh = 3 * (3 - m);
    int smask = (1 << sh) - 1;
    int i = t & 7, sb = t >> 3;
    ull a[8], bq[8];
    #pragma unroll
    for (int j = 0; j < 8; j++) {
        ulonglong2 e = G[i*8 + j];
        a[j] = e.x; bq[j] = e.y;
    }
    for (int k = 0; k < 16; k++) {
        int sl = sb + (k << 5);
        int base = ((sl >> sh) << (sh + 3)) | (sl & smask);
        ull acc = 0ull;
        #pragma unroll
        for (int j = 0; j < 8; j++) {
            ull vp = lds64(in + (unsigned)((base + (j << sh)) << 3));
            ull vs = swp(vp);
            acc = fma2(a[j], vp, acc);
            acc = fma2(bq[j], vs, acc);
        }
        sts64(out + (unsigned)((base + (i << sh)) << 3), acc);
    }
    __syncthreads();
}

__device__ __forceinline__ void apply2(unsigned in, unsigned out,
                                       const ulonglong2* __restrict__ G, int p, int t) {
    int m1 = c_pi[p], m2 = c_pj[p];
    int s1 = 1 << (3 * (3 - m1)), s2 = 1 << (3 * (3 - m2));
    int sa = 1 << (3 * (3 - c_oa[p])), sbb = 1 << (3 * (3 - c_ob[p]));
    int ip = t & 63;
    int i1 = ip >> 3, i2 = ip & 7;
    int tt = i1 + i2;
    int lo = tt > 7 ? tt - 7 : 0;
    int hi = tt < 7 ? tt : 7;
    int cnt = hi - lo + 1;
    ull a[8], bq[8];
    #pragma unroll
    for (int r = 0; r < 8; r++) {
        if (r < cnt) {
            int j1 = lo + r, j2 = tt - j1;
            ulonglong2 e = G[(j1*8 + j2) * 64 + ip];
            a[r] = e.x; bq[r] = e.y;
        }
    }
    int ob0 = t >> 6;
    int dstep = (s1 - s2) << 3;
    for (int k = 0; k < 16; k++) {
        int outer = ob0 + (k << 2);
        int base = (outer >> 3) * sa + (outer & 7) * sbb;
        ull acc = 0ull;
        unsigned addr = in + (unsigned)((base + lo * s1 + (tt - lo) * s2) << 3);
        #pragma unroll
        for (int r = 0; r < 8; r++) {
            if (r < cnt) {
                ull vp = lds64(addr);
                ull vs = swp(vp);
                acc = fma2(a[r], vp, acc);
                acc = fma2(bq[r], vs, acc);
            }
            addr += dstep;
        }
        sts64(out + (unsigned)((base + i1 * s1 + i2 * s2) << 3), acc);
    }
    __syncthreads();
}

extern __shared__ float2 sbuf[];  // 2 x 4096 complex = 64 KB

__global__ void __launch_bounds__(256, 3) sim_kernel(float* out) {
    __shared__ float enc[4][8];
    __shared__ float red[8][4];
    int t = threadIdx.x;
    int b = blockIdx.x;
    unsigned sA = (unsigned)__cvta_generic_to_shared(sbuf);
    unsigned sB = sA + 4096u * 8u;

    if (t < 32) enc[t >> 3][t & 7] = g_enc0[(b * 4 + (t >> 3)) * 8 + (t & 7)];
    __syncthreads();

    // rank-1 initial state: product of encode column-0 vectors (real)
    #pragma unroll
    for (int k = 0; k < 16; k++) {
        int n = t + (k << 8);
        float v = enc[0][(n >> 9) & 7] * enc[1][(n >> 6) & 7]
                * enc[2][(n >> 3) & 7] * enc[3][n & 7];
        sts64(sA + (unsigned)(n << 3), pk(v, 0.f));
    }
    __syncthreads();

    unsigned cur = sA, nxt = sB;
    for (int l = 0; l < 4; l++) {
        for (int p = 0; p < 6; p++) {
            apply2(cur, nxt, g_bs + ((l*2 + 0)*6 + p) * 4096, p, t);
            unsigned tmp = cur; cur = nxt; nxt = tmp;
        }
        for (int w = 0; w < 4; w++) {
            apply1(cur, nxt, g_sq + (l*4 + w) * 64, w, t);
            unsigned tmp = cur; cur = nxt; nxt = tmp;
        }
        for (int p = 0; p < 6; p++) {
            apply2(cur, nxt, g_bs + ((l*2 + 1)*6 + p) * 4096, p, t);
            unsigned tmp = cur; cur = nxt; nxt = tmp;
        }
        for (int w = 0; w < 4; w++) {
            apply1(cur, nxt, g_dp + (l*4 + w) * 64, w, t);
            unsigned tmp = cur; cur = nxt; nxt = tmp;
        }
    }

    // expectation values <n_w>
    float ev0 = 0.f, ev1 = 0.f, ev2 = 0.f, ev3 = 0.f;
    #pragma unroll
    for (int k = 0; k < 16; k++) {
        int n = t + (k << 8);
        float re, im;
        upk(lds64(cur + (unsigned)(n << 3)), re, im);
        float pr = re*re + im*im;
        ev0 += pr * (float)((n >> 9) & 7);
        ev1 += pr * (float)((n >> 6) & 7);
        ev2 += pr * (float)((n >> 3) & 7);
        ev3 += pr * (float)(n & 7);
    }
    #pragma unroll
    for (int off = 16; off; off >>= 1) {
        ev0 += __shfl_xor_sync(0xffffffffu, ev0, off);
        ev1 += __shfl_xor_sync(0xffffffffu, ev1, off);
        ev2 += __shfl_xor_sync(0xffffffffu, ev2, off);
        ev3 += __shfl_xor_sync(0xffffffffu, ev3, off);
    }
    __syncthreads();
    int warp = t >> 5, lane = t & 31;
    if (lane == 0) {
        red[warp][0] = ev0; red[warp][1] = ev1;
        red[warp][2] = ev2; red[warp][3] = ev3;
    }
    __syncthreads();
    if (t < 4) {
        float s = 0.f;
        for (int w = 0; w < 8; w++) s += red[w][t];
        out[b*4 + t] = s;
    }
}

// ---------------- launch ----------------
extern "C" void kernel_launch(void* const* d_in, const int* in_sizes, int n_in,
                              void* d_out, int out_size) {
    const float* x   = (const float*)d_in[0];
    const float* th1 = (const float*)d_in[1];
    const float* ph1 = (const float*)d_in[2];
    const float* th2 = (const float*)d_in[3];
    const float* ph2 = (const float*)d_in[4];
    const float* dr  = (const float*)d_in[5];
    const float* dph = (const float*)d_in[6];
    const float* sr  = (const float*)d_in[7];
    const float* sph = (const float*)d_in[8];
    const float* kr  = (const float*)d_in[9];

    static int smem_set = 0;
    if (!smem_set) {
        cudaFuncSetAttribute(sim_kernel, cudaFuncAttributeMaxDynamicSharedMemorySize, 65536);
        smem_set = 1;
    }

    precompute_kernel<<<3, 256>>>(th1, ph1, th2, ph2, dr, dph, sr, sph, kr);
    encode_kernel<<<64, 256>>>(x);
    sim_kernel<<<NB, 256, 65536>>>((float*)d_out);
}

// round 5
// speedup vs baseline: 2.1199x; 2.1199x over previous
#include <cuda_runtime.h>
#include <math.h>

#define NB 4096

// ---------------- device-global gate storage ----------------
// BS gates [L][2][6], 64x64 complex, TRANSPOSED with diag phases folded:
//   G[(j1*8+j2)*64 + ip] = e^{i b2 i2} * U[ip][jp] * e^{i(a1 j1 + a2 j2)}
__device__ float2 g_bs[48 * 4096];
__device__ float2 g_sq[16 * 64];     // [L][4] 8x8: G[i*8+j] = U[i][j]
__device__ float2 g_dp[16 * 64];     // [L][4] 8x8, Kerr folded on output rows
__device__ float  g_enc0[NB * 4 * 8];// encoding expm column 0 (real)

__constant__ int c_pi[6] = {0,0,0,1,1,2};
__constant__ int c_pj[6] = {1,2,3,2,3,3};
__constant__ int c_oa[6] = {2,1,1,0,0,0};
__constant__ int c_ob[6] = {3,3,2,3,2,1};

// ---------------- small expm (scaling-and-squaring Taylor) ----------------
__device__ void matmul_c(const float2* X, const float2* Y, float2* Z, int n, float scale) {
    for (int i = 0; i < n; i++)
        for (int j = 0; j < n; j++) {
            float ar = 0.f, ai = 0.f;
            for (int m = 0; m < n; m++) {
                float2 a = X[i*8+m], b = Y[m*8+j];
                ar += a.x*b.x - a.y*b.y;
                ai += a.x*b.y + a.y*b.x;
            }
            Z[i*8+j] = make_float2(ar*scale, ai*scale);
        }
}

__device__ void expm_c8(const float2* H, float2* E, int n) {
    float norm = 0.f;
    for (int i = 0; i < n; i++) {
        float r = 0.f;
        for (int j = 0; j < n; j++) r += fabsf(H[i*8+j].x) + fabsf(H[i*8+j].y);
        norm = fmaxf(norm, r);
    }
    int s = 0;
    while (norm > 0.5f && s < 30) { norm *= 0.5f; s++; }
    float sc = ldexpf(1.f, -s);
    float2 T[64], P[64], Q[64];
    for (int i = 0; i < n; i++)
        for (int j = 0; j < n; j++) {
            float2 h = H[i*8+j];
            float2 tv = make_float2(h.x*sc, h.y*sc);
            T[i*8+j] = tv; P[i*8+j] = tv; E[i*8+j] = tv;
        }
    for (int i = 0; i < n; i++) E[i*8+i].x += 1.f;
    for (int k = 2; k <= 16; k++) {
        matmul_c(P, T, Q, n, 1.f/(float)k);
        for (int i = 0; i < n; i++)
            for (int j = 0; j < n; j++) {
                P[i*8+j] = Q[i*8+j];
                E[i*8+j].x += Q[i*8+j].x;
                E[i*8+j].y += Q[i*8+j].y;
            }
    }
    for (int it = 0; it < s; it++) {
        matmul_c(E, E, Q, n, 1.f);
        for (int i = 0; i < n; i++)
            for (int j = 0; j < n; j++) E[i*8+j] = Q[i*8+j];
    }
}

__device__ void matmul_r(const float* X, const float* Y, float* Z, int n, float scale) {
    for (int i = 0; i < n; i++)
        for (int j = 0; j < n; j++) {
            float a = 0.f;
            for (int m = 0; m < n; m++) a += X[i*8+m] * Y[m*8+j];
            Z[i*8+j] = a * scale;
        }
}

__device__ void expm_r8(const float* H, float* E, int n) {
    float norm = 0.f;
    for (int i = 0; i < n; i++) {
        float r = 0.f;
        for (int j = 0; j < n; j++) r += fabsf(H[i*8+j]);
        norm = fmaxf(norm, r);
    }
    int s = 0;
    while (norm > 0.5f && s < 30) { norm *= 0.5f; s++; }
    float sc = ldexpf(1.f, -s);
    float T[64], P[64], Q[64];
    for (int i = 0; i < n; i++)
        for (int j = 0; j < n; j++) {
            float tv = H[i*8+j] * sc;
            T[i*8+j] = tv; P[i*8+j] = tv; E[i*8+j] = tv;
        }
    for (int i = 0; i < n; i++) E[i*8+i] += 1.f;
    for (int k = 2; k <= 16; k++) {
        matmul_r(P, T, Q, n, 1.f/(float)k);
        for (int i = 0; i < n; i++)
            for (int j = 0; j < n; j++) { P[i*8+j] = Q[i*8+j]; E[i*8+j] += Q[i*8+j]; }
    }
    for (int it = 0; it < s; it++) {
        matmul_r(E, E, Q, n, 1.f);
        for (int i = 0; i < n; i++)
            for (int j = 0; j < n; j++) E[i*8+j] = Q[i*8+j];
    }
}

// ---------------- combined precompute + encode ----------------
__global__ void prep_kernel(
    const float* x,
    const float* th1, const float* ph1, const float* th2, const float* ph2,
    const float* dr, const float* dph, const float* sr, const float* sph,
    const float* kerr)
{
    if (blockIdx.x < 64) {
        // per-sample encoding displacement: column 0 of real expm
        int tid = blockIdx.x * 256 + threadIdx.x;
        float xv = x[tid];
        float H[64];
        for (int q = 0; q < 64; q++) H[q] = 0.f;
        for (int ii = 1; ii < 8; ii++) {
            float r = xv * sqrtf((float)ii);
            H[ii*8 + ii-1] = r;
            H[(ii-1)*8 + ii] = -r;
        }
        float E[64];
        expm_r8(H, E, 8);
        float* dst = g_enc0 + tid * 8;
        for (int i = 0; i < 8; i++) dst[i] = E[i*8 + 0];
        return;
    }
    int tid = (blockIdx.x - 64) * 256 + threadIdx.x;
    if (tid < 720) {
        // beamsplitter: one photon-number block per thread (48 gates x 15 totals)
        int g  = tid / 15, tt = tid % 15;
        int l  = g / 12, k = (g / 6) % 2, p = g % 6;
        const float* TH = k ? th2 : th1;
        const float* PH = k ? ph2 : ph1;
        int mi = c_pi[p], mj = c_pj[p];
        float theta = TH[(l*4+mi)*4 + mj];
        float phi   = PH[(l*4+mi)*4 + mj];
        // folded diag phases: input-side (rot-pre first touch), output-side (rot-post)
        float a1 = 0.f, a2 = 0.f;
        if (p == 0) { a1 = PH[(l*4+0)*4 + 0]; a2 = PH[(l*4+1)*4 + 1]; }
        if (p == 1) { a2 = PH[(l*4+2)*4 + 2]; }
        if (p == 2) { a2 = PH[(l*4+3)*4 + 3]; }
        float b2 = PH[(l*4+mj)*4 + mi];
        int lo = tt > 7 ? tt - 7 : 0;
        int hi = tt < 7 ? tt : 7;
        int n  = hi - lo + 1;
        float2 H[64];
        for (int q = 0; q < 64; q++) H[q] = make_float2(0.f, 0.f);
        float cp = cosf(phi), sp = sinf(phi);
        for (int r = 0; r < n; r++) {
            int j1 = lo + r, j2 = tt - j1;
            if (r >= 1) {
                float mag = theta * sqrtf((float)(j1 * (j2 + 1)));
                H[(r-1)*8 + r] = make_float2(mag*cp, mag*sp);
            }
            if (r <= n - 2) {
                float mag = theta * sqrtf((float)((j1 + 1) * j2));
                H[(r+1)*8 + r] = make_float2(-mag*cp, mag*sp);
            }
        }
        float2 E[64];
        expm_c8(H, E, n);
        float2* dst = g_bs + g * 4096;
        for (int ir = 0; ir < n; ir++) {
            int i1 = lo + ir, i2 = tt - i1;
            int ipp = i1 * 8 + i2;
            for (int jr = 0; jr < n; jr++) {
                int j1 = lo + jr, j2 = tt - j1;
                int jpp = j1 * 8 + j2;
                float2 v = E[ir*8 + jr];
                float ang = b2 * (float)i2 + a1 * (float)j1 + a2 * (float)j2;
                float ca = cosf(ang), sa = sinf(ang);
                dst[jpp*64 + ipp] = make_float2(v.x*ca - v.y*sa, v.x*sa + v.y*ca);
            }
        }
    } else if (tid < 736) {
        // squeeze
        int idx = tid - 720;
        float r = sr[idx], p = sph[idx];
        float2 H[64];
        for (int q = 0; q < 64; q++) H[q] = make_float2(0.f, 0.f);
        float cp = cosf(p), sp = sinf(p);
        for (int jj = 2; jj < 8; jj++) {
            float m = 0.5f * r * sqrtf((float)(jj * (jj - 1)));
            H[(jj-2)*8 + jj] = make_float2(m*cp, -m*sp);
            H[jj*8 + jj-2]   = make_float2(-m*cp, -m*sp);
        }
        float2 E[64];
        expm_c8(H, E, 8);
        float2* dst = g_sq + idx * 64;
        for (int i = 0; i < 8; i++)
            for (int j = 0; j < 8; j++) dst[i*8+j] = E[i*8+j];
    } else if (tid < 752) {
        // layer displacement with Kerr folded on output rows
        int idx = tid - 736;
        float r = dr[idx], p = dph[idx];
        float kp = kerr[idx];
        float amag = r * cosf(p);
        float aph  = r * sinf(p);
        float2 al = make_float2(amag * cosf(aph), amag * sinf(aph));
        float2 H[64];
        for (int q = 0; q < 64; q++) H[q] = make_float2(0.f, 0.f);
        for (int ii = 1; ii < 8; ii++) {
            float rt = sqrtf((float)ii);
            H[ii*8 + ii-1] = make_float2(al.x*rt, al.y*rt);
            H[(ii-1)*8 + ii] = make_float2(-al.x*rt, al.y*rt);
        }
        float2 E[64];
        expm_c8(H, E, 8);
        float2* dst = g_dp + idx * 64;
        for (int i = 0; i < 8; i++) {
            float ang = kp * (float)(i * i);
            float ca = cosf(ang), sa = sinf(ang);
            for (int j = 0; j < 8; j++) {
                float2 v = E[i*8+j];
                dst[i*8+j] = make_float2(v.x*ca - v.y*sa, v.x*sa + v.y*ca);
            }
        }
    }
}

// ---------------- main simulation (ping-pong smem, scalar complex FMA) ----------------
__device__ __forceinline__ void apply1(const float2* __restrict__ in, float2* __restrict__ outp,
                                       const float2* __restrict__ G, int m, int t) {
    int sh = 3 * (3 - m);
    int smask = (1 << sh) - 1;
    int i = t & 7, sb = t >> 3;
    float2 g[8];
    #pragma unroll
    for (int j = 0; j < 8; j++) g[j] = G[i*8 + j];
    #pragma unroll 4
    for (int k = 0; k < 16; k++) {
        int sl = sb + (k << 5);
        int base = ((sl >> sh) << (sh + 3)) | (sl & smask);
        float ar = 0.f, ai = 0.f;
        #pragma unroll
        for (int j = 0; j < 8; j++) {
            float2 v = in[base + (j << sh)];
            ar += g[j].x*v.x - g[j].y*v.y;
            ai += g[j].x*v.y + g[j].y*v.x;
        }
        outp[base + (i << sh)] = make_float2(ar, ai);
    }
    __syncthreads();
}

__device__ __forceinline__ void apply2(const float2* __restrict__ in, float2* __restrict__ outp,
                                       const float2* __restrict__ G, int p, int t) {
    int s1 = 1 << (3 * (3 - c_pi[p])), s2 = 1 << (3 * (3 - c_pj[p]));
    int sa = 1 << (3 * (3 - c_oa[p])), sbb = 1 << (3 * (3 - c_ob[p]));
    int ip = t & 63;
    int i1 = ip >> 3, i2 = ip & 7;
    int tt = i1 + i2;
    int lo = tt > 7 ? tt - 7 : 0;
    int hi = tt < 7 ? tt : 7;
    int cnt = hi - lo + 1;
    // photon-number conserving: <=8 nonzero inputs per output
    float2 g[8];
    #pragma unroll
    for (int r = 0; r < 8; r++) {
        if (r < cnt) {
            int j1 = lo + r, j2 = tt - j1;
            g[r] = G[(j1*8 + j2) * 64 + ip];
        }
    }
    int ob0 = t >> 6;
    int dstep = s1 - s2;
    int inbase0 = lo * s1 + (tt - lo) * s2;
    int outoff = i1 * s1 + i2 * s2;
    #pragma unroll 4
    for (int k = 0; k < 16; k++) {
        int outer = ob0 + (k << 2);
        int base = (outer >> 3) * sa + (outer & 7) * sbb;
        float ar = 0.f, ai = 0.f;
        int addr = base + inbase0;
        #pragma unroll
        for (int r = 0; r < 8; r++) {
            if (r < cnt) {
                float2 v = in[addr];
                ar += g[r].x*v.x - g[r].y*v.y;
                ai += g[r].x*v.y + g[r].y*v.x;
            }
            addr += dstep;
        }
        outp[base + outoff] = make_float2(ar, ai);
    }
    __syncthreads();
}

extern __shared__ float2 sbuf[];  // 2 x 4096 complex = 64 KB

__global__ void __launch_bounds__(256) sim_kernel(float* out) {
    __shared__ float enc[4][8];
    __shared__ float red[8][4];
    int t = threadIdx.x;
    int b = blockIdx.x;
    float2* bufA = sbuf;
    float2* bufB = sbuf + 4096;

    if (t < 32) enc[t >> 3][t & 7] = g_enc0[(b * 4 + (t >> 3)) * 8 + (t & 7)];
    __syncthreads();

    // rank-1 initial state: product of encode column-0 vectors (real)
    #pragma unroll
    for (int k = 0; k < 16; k++) {
        int n = t + (k << 8);
        float v = enc[0][(n >> 9) & 7] * enc[1][(n >> 6) & 7]
                * enc[2][(n >> 3) & 7] * enc[3][n & 7];
        bufA[n] = make_float2(v, 0.f);
    }
    __syncthreads();

    float2* cur = bufA;
    float2* nxt = bufB;
    for (int l = 0; l < 4; l++) {
        for (int p = 0; p < 6; p++) {
            apply2(cur, nxt, g_bs + ((l*2 + 0)*6 + p) * 4096, p, t);
            float2* tmp = cur; cur = nxt; nxt = tmp;
        }
        for (int w = 0; w < 4; w++) {
            apply1(cur, nxt, g_sq + (l*4 + w) * 64, w, t);
            float2* tmp = cur; cur = nxt; nxt = tmp;
        }
        for (int p = 0; p < 6; p++) {
            apply2(cur, nxt, g_bs + ((l*2 + 1)*6 + p) * 4096, p, t);
            float2* tmp = cur; cur = nxt; nxt = tmp;
        }
        for (int w = 0; w < 4; w++) {
            apply1(cur, nxt, g_dp + (l*4 + w) * 64, w, t);
            float2* tmp = cur; cur = nxt; nxt = tmp;
        }
    }

    // expectation values <n_w>
    float ev0 = 0.f, ev1 = 0.f, ev2 = 0.f, ev3 = 0.f;
    #pragma unroll
    for (int k = 0; k < 16; k++) {
        int n = t + (k << 8);
        float2 v = cur[n];
        float pr = v.x*v.x + v.y*v.y;
        ev0 += pr * (float)((n >> 9) & 7);
        ev1 += pr * (float)((n >> 6) & 7);
        ev2 += pr * (float)((n >> 3) & 7);
        ev3 += pr * (float)(n & 7);
    }
    #pragma unroll
    for (int off = 16; off; off >>= 1) {
        ev0 += __shfl_xor_sync(0xffffffffu, ev0, off);
        ev1 += __shfl_xor_sync(0xffffffffu, ev1, off);
        ev2 += __shfl_xor_sync(0xffffffffu, ev2, off);
        ev3 += __shfl_xor_sync(0xffffffffu, ev3, off);
    }
    __syncthreads();
    int warp = t >> 5, lane = t & 31;
    if (lane == 0) {
        red[warp][0] = ev0; red[warp][1] = ev1;
        red[warp][2] = ev2; red[warp][3] = ev3;
    }
    __syncthreads();
    if (t < 4) {
        float s = 0.f;
        for (int w = 0; w < 8; w++) s += red[w][t];
        out[b*4 + t] = s;
    }
}

// ---------------- launch ----------------
extern "C" void kernel_launch(void* const* d_in, const int* in_sizes, int n_in,
                              void* d_out, int out_size) {
    const float* x   = (const float*)d_in[0];
    const float* th1 = (const float*)d_in[1];
    const float* ph1 = (const float*)d_in[2];
    const float* th2 = (const float*)d_in[3];
    const float* ph2 = (const float*)d_in[4];
    const float* dr  = (const float*)d_in[5];
    const float* dph = (const float*)d_in[6];
    const float* sr  = (const float*)d_in[7];
    const float* sph = (const float*)d_in[8];
    const float* kr  = (const float*)d_in[9];

    static int smem_set = 0;
    if (!smem_set) {
        cudaFuncSetAttribute(sim_kernel, cudaFuncAttributeMaxDynamicSharedMemorySize, 65536);
        smem_set = 1;
    }

    prep_kernel<<<67, 256>>>(x, th1, ph1, th2, ph2, dr, dph, sr, sph, kr);
    sim_kernel<<<NB, 256, 65536>>>((float*)d_out);
}

// round 6
// speedup vs baseline: 2.8057x; 1.3235x over previous
#include <cuda_runtime.h>
#include <math.h>

typedef unsigned long long ull;

#define NB 4096

// ---------------- device-global gate storage ----------------
// BS gates packed per photon-number diagonal block:
//   g_bs2[gate*344 + OFF[tt] + r*cnt + rr] = packed folded U[(lo+r, tt-lo-r)][(lo+rr, tt-lo-rr)]
// packed entry: .x=(re,re) .y=(im,im) for f32x2 complex MAC
__device__ ulonglong2 g_bs2[48 * 344];
__device__ ulonglong2 g_sq[16 * 64];     // [L][4]: idx j*8+i = U[i][j] packed
__device__ ulonglong2 g_dp[16 * 64];     // [L][4]: Kerr folded on output rows
__device__ float      g_enc0[NB * 4 * 8];// encoding expm column 0 (real)

__constant__ int c_pi[6] = {0,0,0,1,1,2};
__constant__ int c_pj[6] = {1,2,3,2,3,3};
// strides for gate modes and outer modes, per pair p
__constant__ int c_s1[6] = {512,512,512,64,64,8};
__constant__ int c_s2[6] = {64,8,1,8,1,1};
__constant__ int c_sa[6] = {8,64,64,512,512,512};
__constant__ int c_sb[6] = {1,1,8,1,8,64};
// OFF[tt] = cumsum of cnt^2, cnt = 8-|7-tt|
__constant__ int c_off[15] = {0,1,5,14,30,55,91,140,204,253,289,314,330,339,343};

// ---------------- packed helpers ----------------
__device__ __forceinline__ ull pk(float lo, float hi) {
    ull r; asm("mov.b64 %0,{%1,%2};" : "=l"(r) : "f"(lo), "f"(hi)); return r;
}
__device__ __forceinline__ void upk(ull v, float& lo, float& hi) {
    asm("mov.b64 {%0,%1},%2;" : "=f"(lo), "=f"(hi) : "l"(v));
}
__device__ __forceinline__ ull fma2(ull a, ull b, ull c) {
    ull r; asm("fma.rn.f32x2 %0,%1,%2,%3;" : "=l"(r) : "l"(a), "l"(b), "l"(c)); return r;
}
__device__ __forceinline__ ull lds64(unsigned addr) {
    ull r; asm volatile("ld.shared.b64 %0,[%1];" : "=l"(r) : "r"(addr)); return r;
}
__device__ __forceinline__ void sts64(unsigned addr, ull v) {
    asm volatile("st.shared.b64 [%0],%1;" :: "r"(addr), "l"(v));
}
__device__ __forceinline__ ulonglong2 pks(float re, float im) {
    ulonglong2 r; r.x = pk(re, re); r.y = pk(im, im); return r;
}
// bank-spreading swizzle (bijective within each 16-element block)
__device__ __forceinline__ int phys(int e) {
    return e ^ ((e >> 4) & 15) ^ ((e >> 8) & 15);
}

// ---------------- small expm (scaling-and-squaring Taylor) ----------------
__device__ void matmul_c(const float2* X, const float2* Y, float2* Z, int n, float scale) {
    for (int i = 0; i < n; i++)
        for (int j = 0; j < n; j++) {
            float ar = 0.f, ai = 0.f;
            for (int m = 0; m < n; m++) {
                float2 a = X[i*8+m], b = Y[m*8+j];
                ar += a.x*b.x - a.y*b.y;
                ai += a.x*b.y + a.y*b.x;
            }
            Z[i*8+j] = make_float2(ar*scale, ai*scale);
        }
}

__device__ void expm_c8(const float2* H, float2* E, int n) {
    float norm = 0.f;
    for (int i = 0; i < n; i++) {
        float r = 0.f;
        for (int j = 0; j < n; j++) r += fabsf(H[i*8+j].x) + fabsf(H[i*8+j].y);
        norm = fmaxf(norm, r);
    }
    int s = 0;
    while (norm > 0.5f && s < 30) { norm *= 0.5f; s++; }
    float sc = ldexpf(1.f, -s);
    float2 T[64], P[64], Q[64];
    for (int i = 0; i < n; i++)
        for (int j = 0; j < n; j++) {
            float2 h = H[i*8+j];
            float2 tv = make_float2(h.x*sc, h.y*sc);
            T[i*8+j] = tv; P[i*8+j] = tv; E[i*8+j] = tv;
        }
    for (int i = 0; i < n; i++) E[i*8+i].x += 1.f;
    for (int k = 2; k <= 16; k++) {
        matmul_c(P, T, Q, n, 1.f/(float)k);
        for (int i = 0; i < n; i++)
            for (int j = 0; j < n; j++) {
                P[i*8+j] = Q[i*8+j];
                E[i*8+j].x += Q[i*8+j].x;
                E[i*8+j].y += Q[i*8+j].y;
            }
    }
    for (int it = 0; it < s; it++) {
        matmul_c(E, E, Q, n, 1.f);
        for (int i = 0; i < n; i++)
            for (int j = 0; j < n; j++) E[i*8+j] = Q[i*8+j];
    }
}

__device__ void matmul_r(const float* X, const float* Y, float* Z, int n, float scale) {
    for (int i = 0; i < n; i++)
        for (int j = 0; j < n; j++) {
            float a = 0.f;
            for (int m = 0; m < n; m++) a += X[i*8+m] * Y[m*8+j];
            Z[i*8+j] = a * scale;
        }
}

__device__ void expm_r8(const float* H, float* E, int n) {
    float norm = 0.f;
    for (int i = 0; i < n; i++) {
        float r = 0.f;
        for (int j = 0; j < n; j++) r += fabsf(H[i*8+j]);
        norm = fmaxf(norm, r);
    }
    int s = 0;
    while (norm > 0.5f && s < 30) { norm *= 0.5f; s++; }
    float sc = ldexpf(1.f, -s);
    float T[64], P[64], Q[64];
    for (int i = 0; i < n; i++)
        for (int j = 0; j < n; j++) {
            float tv = H[i*8+j] * sc;
            T[i*8+j] = tv; P[i*8+j] = tv; E[i*8+j] = tv;
        }
    for (int i = 0; i < n; i++) E[i*8+i] += 1.f;
    for (int k = 2; k <= 16; k++) {
        matmul_r(P, T, Q, n, 1.f/(float)k);
        for (int i = 0; i < n; i++)
            for (int j = 0; j < n; j++) { P[i*8+j] = Q[i*8+j]; E[i*8+j] += Q[i*8+j]; }
    }
    for (int it = 0; it < s; it++) {
        matmul_r(E, E, Q, n, 1.f);
        for (int i = 0; i < n; i++)
            for (int j = 0; j < n; j++) E[i*8+j] = Q[i*8+j];
    }
}

// ---------------- combined precompute + encode ----------------
__global__ void prep_kernel(
    const float* x,
    const float* th1, const float* ph1, const float* th2, const float* ph2,
    const float* dr, const float* dph, const float* sr, const float* sph,
    const float* kerr)
{
    if (blockIdx.x < 64) {
        // per-sample encoding displacement: column 0 of real expm
        int tid = blockIdx.x * 256 + threadIdx.x;
        float xv = x[tid];
        float H[64];
        for (int q = 0; q < 64; q++) H[q] = 0.f;
        for (int ii = 1; ii < 8; ii++) {
            float r = xv * sqrtf((float)ii);
            H[ii*8 + ii-1] = r;
            H[(ii-1)*8 + ii] = -r;
        }
        float E[64];
        expm_r8(H, E, 8);
        float* dst = g_enc0 + tid * 8;
        for (int i = 0; i < 8; i++) dst[i] = E[i*8 + 0];
        return;
    }
    int tid = (blockIdx.x - 64) * 256 + threadIdx.x;
    if (tid < 720) {
        // beamsplitter: one photon-number diagonal block per thread
        int g  = tid / 15, tt = tid % 15;
        int l  = g / 12, k = (g / 6) % 2, p = g % 6;
        const float* TH = k ? th2 : th1;
        const float* PH = k ? ph2 : ph1;
        int mi = c_pi[p], mj = c_pj[p];
        float theta = TH[(l*4+mi)*4 + mj];
        float phi   = PH[(l*4+mi)*4 + mj];
        // folded diag phases: input-side rot-pre (first touch per mode), output-side rot-post
        float a1 = 0.f, a2 = 0.f;
        if (p == 0) { a1 = PH[(l*4+0)*4 + 0]; a2 = PH[(l*4+1)*4 + 1]; }
        if (p == 1) { a2 = PH[(l*4+2)*4 + 2]; }
        if (p == 2) { a2 = PH[(l*4+3)*4 + 3]; }
        float b2 = PH[(l*4+mj)*4 + mi];
        int lo = tt > 7 ? tt - 7 : 0;
        int hi = tt < 7 ? tt : 7;
        int n  = hi - lo + 1;
        float2 H[64];
        for (int q = 0; q < 64; q++) H[q] = make_float2(0.f, 0.f);
        float cp = cosf(phi), sp = sinf(phi);
        for (int r = 0; r < n; r++) {
            int j1 = lo + r, j2 = tt - j1;
            if (r >= 1) {
                float mag = theta * sqrtf((float)(j1 * (j2 + 1)));
                H[(r-1)*8 + r] = make_float2(mag*cp, mag*sp);
            }
            if (r <= n - 2) {
                float mag = theta * sqrtf((float)((j1 + 1) * j2));
                H[(r+1)*8 + r] = make_float2(-mag*cp, mag*sp);
            }
        }
        float2 E[64];
        expm_c8(H, E, n);
        ulonglong2* dst = g_bs2 + g * 344 + c_off[tt];
        for (int ir = 0; ir < n; ir++) {
            int i1 = lo + ir, i2 = tt - i1;
            for (int jr = 0; jr < n; jr++) {
                int j1 = lo + jr, j2 = tt - j1;
                float2 v = E[ir*8 + jr];
                float ang = b2 * (float)i2 + a1 * (float)j1 + a2 * (float)j2;
                float ca = cosf(ang), sa = sinf(ang);
                dst[ir*n + jr] = pks(v.x*ca - v.y*sa, v.x*sa + v.y*ca);
            }
        }
    } else if (tid < 736) {
        // squeeze
        int idx = tid - 720;
        float r = sr[idx], p = sph[idx];
        float2 H[64];
        for (int q = 0; q < 64; q++) H[q] = make_float2(0.f, 0.f);
        float cp = cosf(p), sp = sinf(p);
        for (int jj = 2; jj < 8; jj++) {
            float m = 0.5f * r * sqrtf((float)(jj * (jj - 1)));
            H[(jj-2)*8 + jj] = make_float2(m*cp, -m*sp);
            H[jj*8 + jj-2]   = make_float2(-m*cp, -m*sp);
        }
        float2 E[64];
        expm_c8(H, E, 8);
        ulonglong2* dst = g_sq + idx * 64;
        for (int i = 0; i < 8; i++)
            for (int j = 0; j < 8; j++)
                dst[j*8+i] = pks(E[i*8+j].x, E[i*8+j].y);   // idx j*8+i = U[i][j]
    } else if (tid < 752) {
        // layer displacement with Kerr folded on output rows
        int idx = tid - 736;
        float r = dr[idx], p = dph[idx];
        float kp = kerr[idx];
        float amag = r * cosf(p);
        float aph  = r * sinf(p);
        float2 al = make_float2(amag * cosf(aph), amag * sinf(aph));
        float2 H[64];
        for (int q = 0; q < 64; q++) H[q] = make_float2(0.f, 0.f);
        for (int ii = 1; ii < 8; ii++) {
            float rt = sqrtf((float)ii);
            H[ii*8 + ii-1] = make_float2(al.x*rt, al.y*rt);
            H[(ii-1)*8 + ii] = make_float2(-al.x*rt, al.y*rt);
        }
        float2 E[64];
        expm_c8(H, E, 8);
        ulonglong2* dst = g_dp + idx * 64;
        for (int i = 0; i < 8; i++) {
            float ang = kp * (float)(i * i);
            float ca = cosf(ang), sa = sinf(ang);
            for (int j = 0; j < 8; j++) {
                float2 v = E[i*8+j];
                dst[j*8+i] = pks(v.x*ca - v.y*sa, v.x*sa + v.y*ca);
            }
        }
    }
}

// ---------------- main simulation: in-place, ownership-partitioned ----------------

// single-mode gate: each thread owns 2 full lines (8 amplitudes along mode m)
__device__ __forceinline__ void apply1(unsigned sb, const ulonglong2* __restrict__ G,
                                       int m, int t) {
    int sh = 3 * (3 - m);
    int smask = (1 << sh) - 1;
    #pragma unroll
    for (int q = 0; q < 2; q++) {
        int sl = 2*t + q;
        int base = ((sl >> sh) << (sh + 3)) | (sl & smask);
        ull aA[8], aB[8];
        #pragma unroll
        for (int i = 0; i < 8; i++) { aA[i] = 0ull; aB[i] = 0ull; }
        #pragma unroll
        for (int j = 0; j < 8; j++) {
            int e = base + (j << sh);
            ull v = lds64(sb + (unsigned)(phys(e) << 3));
            #pragma unroll
            for (int i = 0; i < 8; i++) {
                ulonglong2 gg = G[j*8 + i];       // warp-uniform LDG.128
                aA[i] = fma2(gg.x, v, aA[i]);
                aB[i] = fma2(gg.y, v, aB[i]);
            }
        }
        #pragma unroll
        for (int i = 0; i < 8; i++) {
            float a0, a1, b0, b1;
            upk(aA[i], a0, a1); upk(aB[i], b0, b1);
            int e = base + (i << sh);
            sts64(sb + (unsigned)(phys(e) << 3), pk(a0 - b1, a1 + b0));
        }
    }
    __syncthreads();
}

// one photon-number diagonal of a 2-mode plane: cnt x cnt in-place matvec
template<int CNT>
__device__ __forceinline__ void diagf(unsigned sb, int e0, int step,
                                      const ulonglong2* __restrict__ G) {
    ull aA[CNT], aB[CNT];
    #pragma unroll
    for (int r = 0; r < CNT; r++) { aA[r] = 0ull; aB[r] = 0ull; }
    #pragma unroll
    for (int rr = 0; rr < CNT; rr++) {
        ull v = lds64(sb + (unsigned)(phys(e0 + rr*step) << 3));
        #pragma unroll
        for (int r = 0; r < CNT; r++) {
            ulonglong2 gg = G[r*CNT + rr];        // warp-uniform LDG.128
            aA[r] = fma2(gg.x, v, aA[r]);
            aB[r] = fma2(gg.y, v, aB[r]);
        }
    }
    #pragma unroll
    for (int r = 0; r < CNT; r++) {
        float a0, a1, b0, b1;
        upk(aA[r], a0, a1); upk(aB[r], b0, b1);
        sts64(sb + (unsigned)(phys(e0 + r*step) << 3), pk(a0 - b1, a1 + b0));
    }
}

// two-mode BS gate: warp-per-diag-group, lane-per-plane, in place
__device__ __forceinline__ void apply2(unsigned sb, const ulonglong2* __restrict__ GB,
                                       int p, int t) {
    int s1 = c_s1[p], s2 = c_s2[p], sa = c_sa[p], sbs = c_sb[p];
    int w = t >> 5, lane = t & 31;
    int grp = w & 3;
    int o = ((w >> 2) << 5) | lane;                 // plane 0..63
    int base = (o >> 3) * sa + (o & 7) * sbs;
    int step = s1 - s2;
    if (grp == 0) {          // MACs 64+25 = 89
        diagf<8>(sb, base + 7*s2,          step, GB + 140);   // tt=7
        diagf<5>(sb, base + 4*s2,          step, GB + 30);    // tt=4
    } else if (grp == 1) {   // 49+36 = 85
        diagf<7>(sb, base + 6*s2,          step, GB + 91);    // tt=6
        diagf<6>(sb, base + 5*s2,          step, GB + 55);    // tt=5
    } else if (grp == 2) {   // 49+36 = 85
        diagf<7>(sb, base + s1   + 7*s2,   step, GB + 204);   // tt=8
        diagf<6>(sb, base + 2*s1 + 7*s2,   step, GB + 253);   // tt=9
    } else {                 // 1+4+9+16+25+16+9+4+1 = 85
        diagf<1>(sb, base,                 step, GB + 0);     // tt=0
        diagf<2>(sb, base + s2,            step, GB + 1);     // tt=1
        diagf<3>(sb, base + 2*s2,          step, GB + 5);     // tt=2
        diagf<4>(sb, base + 3*s2,          step, GB + 14);    // tt=3
        diagf<5>(sb, base + 3*s1 + 7*s2,   step, GB + 289);   // tt=10
        diagf<4>(sb, base + 4*s1 + 7*s2,   step, GB + 314);   // tt=11
        diagf<3>(sb, base + 5*s1 + 7*s2,   step, GB + 330);   // tt=12
        diagf<2>(sb, base + 6*s1 + 7*s2,   step, GB + 339);   // tt=13
        diagf<1>(sb, base + 7*s1 + 7*s2,   step, GB + 343);   // tt=14
    }
    __syncthreads();
}

__global__ void __launch_bounds__(256) sim_kernel(float* out) {
    __shared__ float2 st[4096];
    __shared__ float enc[4][8];
    __shared__ float red[8][4];
    int t = threadIdx.x;
    int b = blockIdx.x;
    unsigned sb = (unsigned)__cvta_generic_to_shared(st);

    if (t < 32) enc[t >> 3][t & 7] = g_enc0[(b * 4 + (t >> 3)) * 8 + (t & 7)];
    __syncthreads();

    // rank-1 initial state: product of encode column-0 vectors (real)
    #pragma unroll
    for (int k = 0; k < 16; k++) {
        int n = t + (k << 8);
        float v = enc[0][(n >> 9) & 7] * enc[1][(n >> 6) & 7]
                * enc[2][(n >> 3) & 7] * enc[3][n & 7];
        sts64(sb + (unsigned)(phys(n) << 3), pk(v, 0.f));
    }
    __syncthreads();

    for (int l = 0; l < 4; l++) {
        for (int p = 0; p < 6; p++)
            apply2(sb, g_bs2 + ((l*2 + 0)*6 + p) * 344, p, t);
        for (int w = 0; w < 4; w++)
            apply1(sb, g_sq + (l*4 + w) * 64, w, t);
        for (int p = 0; p < 6; p++)
            apply2(sb, g_bs2 + ((l*2 + 1)*6 + p) * 344, p, t);
        for (int w = 0; w < 4; w++)
            apply1(sb, g_dp + (l*4 + w) * 64, w, t);
    }

    // expectation values <n_w>
    float ev0 = 0.f, ev1 = 0.f, ev2 = 0.f, ev3 = 0.f;
    #pragma unroll
    for (int k = 0; k < 16; k++) {
        int n = t + (k << 8);
        float re, im;
        upk(lds64(sb + (unsigned)(phys(n) << 3)), re, im);
        float pr = re*re + im*im;
        ev0 += pr * (float)((n >> 9) & 7);
        ev1 += pr * (float)((n >> 6) & 7);
        ev2 += pr * (float)((n >> 3) & 7);
        ev3 += pr * (float)(n & 7);
    }
    #pragma unroll
    for (int off = 16; off; off >>= 1) {
        ev0 += __shfl_xor_sync(0xffffffffu, ev0, off);
        ev1 += __shfl_xor_sync(0xffffffffu, ev1, off);
        ev2 += __shfl_xor_sync(0xffffffffu, ev2, off);
        ev3 += __shfl_xor_sync(0xffffffffu, ev3, off);
    }
    __syncthreads();
    int warp = t >> 5, lane = t & 31;
    if (lane == 0) {
        red[warp][0] = ev0; red[warp][1] = ev1;
        red[warp][2] = ev2; red[warp][3] = ev3;
    }
    __syncthreads();
    if (t < 4) {
        float s = 0.f;
        for (int w = 0; w < 8; w++) s += red[w][t];
        out[b*4 + t] = s;
    }
}

// ---------------- launch ----------------
extern "C" void kernel_launch(void* const* d_in, const int* in_sizes, int n_in,
                              void* d_out, int out_size) {
    const float* x   = (const float*)d_in[0];
    const float* th1 = (const float*)d_in[1];
    const float* ph1 = (const float*)d_in[2];
    const float* th2 = (const float*)d_in[3];
    const float* ph2 = (const float*)d_in[4];
    const float* dr  = (const float*)d_in[5];
    const float* dph = (const float*)d_in[6];
    const float* sr  = (const float*)d_in[7];
    const float* sph = (const float*)d_in[8];
    const float* kr  = (const float*)d_in[9];

    prep_kernel<<<67, 256>>>(x, th1, ph1, th2, ph2, dr, dph, sr, sph, kr);
    sim_kernel<<<NB, 256>>>((float*)d_out);
}

// round 7
// speedup vs baseline: 4.6766x; 1.6669x over previous
#include <cuda_runtime.h>
#include <math.h>

typedef unsigned long long ull;

#define NB 4096

// ---------------- device-global gate storage ----------------
// BS gates packed per photon-number diagonal block:
//   g_bs2[gate*344 + OFF[tt] + r*cnt + rr] = packed folded U[out r][in rr]
// packed entry: .x=(re,re) .y=(im,im) for f32x2 complex MAC
__device__ ulonglong2 g_bs2[48 * 344];
__device__ ulonglong2 g_sq[16 * 64];     // [L][4]: idx j*8+i = U[i][j] packed
__device__ ulonglong2 g_dp[16 * 64];     // [L][4]: Kerr folded on output rows
__device__ float      g_enc0[NB * 4 * 8];// encoding expm column 0 (real)

__constant__ int c_pi[6] = {0,0,0,1,1,2};
__constant__ int c_pj[6] = {1,2,3,2,3,3};
// strides for gate modes and outer modes, per pair p
__constant__ int c_s1[6] = {512,512,512,64,64,8};
__constant__ int c_s2[6] = {64,8,1,8,1,1};
__constant__ int c_sa[6] = {8,64,64,512,512,512};
__constant__ int c_sb[6] = {1,1,8,1,8,64};
// OFF[tt] = cumsum of cnt^2, cnt = 8-|7-tt|
__constant__ int c_off[15] = {0,1,5,14,30,55,91,140,204,253,289,314,330,339,343};

// ---------------- packed helpers ----------------
__device__ __forceinline__ ull pk(float lo, float hi) {
    ull r; asm("mov.b64 %0,{%1,%2};" : "=l"(r) : "f"(lo), "f"(hi)); return r;
}
__device__ __forceinline__ void upk(ull v, float& lo, float& hi) {
    asm("mov.b64 {%0,%1},%2;" : "=f"(lo), "=f"(hi) : "l"(v));
}
__device__ __forceinline__ ull fma2(ull a, ull b, ull c) {
    ull r; asm("fma.rn.f32x2 %0,%1,%2,%3;" : "=l"(r) : "l"(a), "l"(b), "l"(c)); return r;
}
__device__ __forceinline__ ull lds64(unsigned addr) {
    ull r; asm volatile("ld.shared.b64 %0,[%1];" : "=l"(r) : "r"(addr)); return r;
}
__device__ __forceinline__ void sts64(unsigned addr, ull v) {
    asm volatile("st.shared.b64 [%0],%1;" :: "r"(addr), "l"(v));
}
__device__ __forceinline__ ulonglong2 lds128(unsigned addr) {
    ulonglong2 r;
    asm volatile("ld.shared.v2.u64 {%0,%1},[%2];" : "=l"(r.x), "=l"(r.y) : "r"(addr));
    return r;
}
__device__ __forceinline__ void cpa16(unsigned dst, const void* src) {
    asm volatile("cp.async.ca.shared.global [%0],[%1],16;" :: "r"(dst), "l"(src));
}
__device__ __forceinline__ ulonglong2 pks(float re, float im) {
    ulonglong2 r; r.x = pk(re, re); r.y = pk(im, im); return r;
}
// bank-spreading swizzle (bijective within each 16-element block)
__device__ __forceinline__ int phys(int e) {
    return e ^ ((e >> 4) & 15) ^ ((e >> 8) & 15);
}

// ---------------- small expm (scaling-and-squaring Taylor) ----------------
__device__ void matmul_c(const float2* X, const float2* Y, float2* Z, int n, float scale) {
    for (int i = 0; i < n; i++)
        for (int j = 0; j < n; j++) {
            float ar = 0.f, ai = 0.f;
            for (int m = 0; m < n; m++) {
                float2 a = X[i*8+m], b = Y[m*8+j];
                ar += a.x*b.x - a.y*b.y;
                ai += a.x*b.y + a.y*b.x;
            }
            Z[i*8+j] = make_float2(ar*scale, ai*scale);
        }
}

__device__ void expm_c8(const float2* H, float2* E, int n) {
    float norm = 0.f;
    for (int i = 0; i < n; i++) {
        float r = 0.f;
        for (int j = 0; j < n; j++) r += fabsf(H[i*8+j].x) + fabsf(H[i*8+j].y);
        norm = fmaxf(norm, r);
    }
    int s = 0;
    while (norm > 0.5f && s < 30) { norm *= 0.5f; s++; }
    float sc = ldexpf(1.f, -s);
    float2 T[64], P[64], Q[64];
    for (int i = 0; i < n; i++)
        for (int j = 0; j < n; j++) {
            float2 h = H[i*8+j];
            float2 tv = make_float2(h.x*sc, h.y*sc);
            T[i*8+j] = tv; P[i*8+j] = tv; E[i*8+j] = tv;
        }
    for (int i = 0; i < n; i++) E[i*8+i].x += 1.f;
    for (int k = 2; k <= 16; k++) {
        matmul_c(P, T, Q, n, 1.f/(float)k);
        for (int i = 0; i < n; i++)
            for (int j = 0; j < n; j++) {
                P[i*8+j] = Q[i*8+j];
                E[i*8+j].x += Q[i*8+j].x;
                E[i*8+j].y += Q[i*8+j].y;
            }
    }
    for (int it = 0; it < s; it++) {
        matmul_c(E, E, Q, n, 1.f);
        for (int i = 0; i < n; i++)
            for (int j = 0; j < n; j++) E[i*8+j] = Q[i*8+j];
    }
}

__device__ void matmul_r(const float* X, const float* Y, float* Z, int n, float scale) {
    for (int i = 0; i < n; i++)
        for (int j = 0; j < n; j++) {
            float a = 0.f;
            for (int m = 0; m < n; m++) a += X[i*8+m] * Y[m*8+j];
            Z[i*8+j] = a * scale;
        }
}

__device__ void expm_r8(const float* H, float* E, int n) {
    float norm = 0.f;
    for (int i = 0; i < n; i++) {
        float r = 0.f;
        for (int j = 0; j < n; j++) r += fabsf(H[i*8+j]);
        norm = fmaxf(norm, r);
    }
    int s = 0;
    while (norm > 0.5f && s < 30) { norm *= 0.5f; s++; }
    float sc = ldexpf(1.f, -s);
    float T[64], P[64], Q[64];
    for (int i = 0; i < n; i++)
        for (int j = 0; j < n; j++) {
            float tv = H[i*8+j] * sc;
            T[i*8+j] = tv; P[i*8+j] = tv; E[i*8+j] = tv;
        }
    for (int i = 0; i < n; i++) E[i*8+i] += 1.f;
    for (int k = 2; k <= 16; k++) {
        matmul_r(P, T, Q, n, 1.f/(float)k);
        for (int i = 0; i < n; i++)
            for (int j = 0; j < n; j++) { P[i*8+j] = Q[i*8+j]; E[i*8+j] += Q[i*8+j]; }
    }
    for (int it = 0; it < s; it++) {
        matmul_r(E, E, Q, n, 1.f);
        for (int i = 0; i < n; i++)
            for (int j = 0; j < n; j++) E[i*8+j] = Q[i*8+j];
    }
}

// ---------------- combined precompute + encode ----------------
__global__ void prep_kernel(
    const float* x,
    const float* th1, const float* ph1, const float* th2, const float* ph2,
    const float* dr, const float* dph, const float* sr, const float* sph,
    const float* kerr)
{
    if (blockIdx.x < 64) {
        // per-sample encoding displacement: column 0 of real expm
        int tid = blockIdx.x * 256 + threadIdx.x;
        float xv = x[tid];
        float H[64];
        for (int q = 0; q < 64; q++) H[q] = 0.f;
        for (int ii = 1; ii < 8; ii++) {
            float r = xv * sqrtf((float)ii);
            H[ii*8 + ii-1] = r;
            H[(ii-1)*8 + ii] = -r;
        }
        float E[64];
        expm_r8(H, E, 8);
        float* dst = g_enc0 + tid * 8;
        for (int i = 0; i < 8; i++) dst[i] = E[i*8 + 0];
        return;
    }
    int tid = (blockIdx.x - 64) * 256 + threadIdx.x;
    if (tid < 720) {
        // beamsplitter: one photon-number diagonal block per thread
        int g  = tid / 15, tt = tid % 15;
        int l  = g / 12, k = (g / 6) % 2, p = g % 6;
        const float* TH = k ? th2 : th1;
        const float* PH = k ? ph2 : ph1;
        int mi = c_pi[p], mj = c_pj[p];
        float theta = TH[(l*4+mi)*4 + mj];
        float phi   = PH[(l*4+mi)*4 + mj];
        // folded diag phases: input-side rot-pre (first touch per mode), output-side rot-post
        float a1 = 0.f, a2 = 0.f;
        if (p == 0) { a1 = PH[(l*4+0)*4 + 0]; a2 = PH[(l*4+1)*4 + 1]; }
        if (p == 1) { a2 = PH[(l*4+2)*4 + 2]; }
        if (p == 2) { a2 = PH[(l*4+3)*4 + 3]; }
        float b2 = PH[(l*4+mj)*4 + mi];
        int lo = tt > 7 ? tt - 7 : 0;
        int hi = tt < 7 ? tt : 7;
        int n  = hi - lo + 1;
        float2 H[64];
        for (int q = 0; q < 64; q++) H[q] = make_float2(0.f, 0.f);
        float cp = cosf(phi), sp = sinf(phi);
        for (int r = 0; r < n; r++) {
            int j1 = lo + r, j2 = tt - j1;
            if (r >= 1) {
                float mag = theta * sqrtf((float)(j1 * (j2 + 1)));
                H[(r-1)*8 + r] = make_float2(mag*cp, mag*sp);
            }
            if (r <= n - 2) {
                float mag = theta * sqrtf((float)((j1 + 1) * j2));
                H[(r+1)*8 + r] = make_float2(-mag*cp, mag*sp);
            }
        }
        float2 E[64];
        expm_c8(H, E, n);
        ulonglong2* dst = g_bs2 + g * 344 + c_off[tt];
        for (int ir = 0; ir < n; ir++) {
            int i1 = lo + ir, i2 = tt - i1;
            for (int jr = 0; jr < n; jr++) {
                int j1 = lo + jr, j2 = tt - j1;
                float2 v = E[ir*8 + jr];
                float ang = b2 * (float)i2 + a1 * (float)j1 + a2 * (float)j2;
                float ca = cosf(ang), sa = sinf(ang);
                dst[ir*n + jr] = pks(v.x*ca - v.y*sa, v.x*sa + v.y*ca);
            }
        }
    } else if (tid < 736) {
        // squeeze
        int idx = tid - 720;
        float r = sr[idx], p = sph[idx];
        float2 H[64];
        for (int q = 0; q < 64; q++) H[q] = make_float2(0.f, 0.f);
        float cp = cosf(p), sp = sinf(p);
        for (int jj = 2; jj < 8; jj++) {
            float m = 0.5f * r * sqrtf((float)(jj * (jj - 1)));
            H[(jj-2)*8 + jj] = make_float2(m*cp, -m*sp);
            H[jj*8 + jj-2]   = make_float2(-m*cp, -m*sp);
        }
        float2 E[64];
        expm_c8(H, E, 8);
        ulonglong2* dst = g_sq + idx * 64;
        for (int i = 0; i < 8; i++)
            for (int j = 0; j < 8; j++)
                dst[j*8+i] = pks(E[i*8+j].x, E[i*8+j].y);   // idx j*8+i = U[i][j]
    } else if (tid < 752) {
        // layer displacement with Kerr folded on output rows
        int idx = tid - 736;
        float r = dr[idx], p = dph[idx];
        float kp = kerr[idx];
        float amag = r * cosf(p);
        float aph  = r * sinf(p);
        float2 al = make_float2(amag * cosf(aph), amag * sinf(aph));
        float2 H[64];
        for (int q = 0; q < 64; q++) H[q] = make_float2(0.f, 0.f);
        for (int ii = 1; ii < 8; ii++) {
            float rt = sqrtf((float)ii);
            H[ii*8 + ii-1] = make_float2(al.x*rt, al.y*rt);
            H[(ii-1)*8 + ii] = make_float2(-al.x*rt, al.y*rt);
        }
        float2 E[64];
        expm_c8(H, E, 8);
        ulonglong2* dst = g_dp + idx * 64;
        for (int i = 0; i < 8; i++) {
            float ang = kp * (float)(i * i);
            float ca = cosf(ang), sa = sinf(ang);
            for (int j = 0; j < 8; j++) {
                float2 v = E[i*8+j];
                dst[j*8+i] = pks(v.x*ca - v.y*sa, v.x*sa + v.y*ca);
            }
        }
    }
}

// ---------------- pass descriptor ----------------
__device__ __forceinline__ void pdesc(int k, const ulonglong2*& src, int& n, int& ty, int& pm) {
    int l = k / 20, r = k - l*20;
    if (r < 6)       { src = g_bs2 + ((2*l)*6 + r)*344;          n = 344; ty = 2; pm = r; }
    else if (r < 10) { src = g_sq + (l*4 + (r-6))*64;            n = 64;  ty = 1; pm = r-6; }
    else if (r < 16) { src = g_bs2 + ((2*l+1)*6 + (r-10))*344;   n = 344; ty = 2; pm = r-10; }
    else             { src = g_dp + (l*4 + (r-16))*64;           n = 64;  ty = 1; pm = r-16; }
}

// ---------------- main simulation: in-place ownership, gates via smem stream ----------------

// single-mode gate: each thread owns 2 full lines; gates streamed from smem (broadcast)
__device__ __forceinline__ void apply1s(unsigned sb, unsigned gb, int m, int t) {
    int sh = 3 * (3 - m);
    int smask = (1 << sh) - 1;
    int sl0 = 2*t, sl1 = 2*t + 1;
    int base0 = ((sl0 >> sh) << (sh + 3)) | (sl0 & smask);
    int base1 = ((sl1 >> sh) << (sh + 3)) | (sl1 & smask);
    ull aA0[8], aB0[8], aA1[8], aB1[8];
    #pragma unroll
    for (int i = 0; i < 8; i++) { aA0[i]=0ull; aB0[i]=0ull; aA1[i]=0ull; aB1[i]=0ull; }
    #pragma unroll 1
    for (int j = 0; j < 8; j++) {
        ull v0 = lds64(sb + (unsigned)(phys(base0 + (j << sh)) << 3));
        ull v1 = lds64(sb + (unsigned)(phys(base1 + (j << sh)) << 3));
        #pragma unroll
        for (int i = 0; i < 8; i++) {
            ulonglong2 gg = lds128(gb + (unsigned)((j*8 + i) << 4));
            aA0[i] = fma2(gg.x, v0, aA0[i]); aB0[i] = fma2(gg.y, v0, aB0[i]);
            aA1[i] = fma2(gg.x, v1, aA1[i]); aB1[i] = fma2(gg.y, v1, aB1[i]);
        }
    }
    #pragma unroll
    for (int i = 0; i < 8; i++) {
        float a0, a1, b0, b1;
        upk(aA0[i], a0, a1); upk(aB0[i], b0, b1);
        sts64(sb + (unsigned)(phys(base0 + (i << sh)) << 3), pk(a0 - b1, a1 + b0));
        upk(aA1[i], a0, a1); upk(aB1[i], b0, b1);
        sts64(sb + (unsigned)(phys(base1 + (i << sh)) << 3), pk(a0 - b1, a1 + b0));
    }
}

// one photon-number diagonal of a 2-mode plane: cnt x cnt in-place matvec
template<int CNT>
__device__ __forceinline__ void diagfs(unsigned sb, int e0, int step, unsigned g) {
    ull aA[CNT], aB[CNT];
    #pragma unroll
    for (int r = 0; r < CNT; r++) { aA[r] = 0ull; aB[r] = 0ull; }
    #pragma unroll 1
    for (int rr = 0; rr < CNT; rr++) {
        ull v = lds64(sb + (unsigned)(phys(e0 + rr*step) << 3));
        #pragma unroll
        for (int r = 0; r < CNT; r++) {
            ulonglong2 gg = lds128(g + (unsigned)((r*CNT + rr) << 4));
            aA[r] = fma2(gg.x, v, aA[r]);
            aB[r] = fma2(gg.y, v, aB[r]);
        }
    }
    #pragma unroll
    for (int r = 0; r < CNT; r++) {
        float a0, a1, b0, b1;
        upk(aA[r], a0, a1); upk(aB[r], b0, b1);
        sts64(sb + (unsigned)(phys(e0 + r*step) << 3), pk(a0 - b1, a1 + b0));
    }
}

// two-mode BS gate: warp-per-diag-group, lane-per-plane, in place
__device__ __forceinline__ void apply2s(unsigned sb, unsigned gb, int p, int t) {
    int s1 = c_s1[p], s2 = c_s2[p], sa = c_sa[p], sbs = c_sb[p];
    int w = t >> 5, lane = t & 31;
    int grp = w & 3;
    int o = ((w >> 2) << 5) | lane;                 // plane 0..63
    int base = (o >> 3) * sa + (o & 7) * sbs;
    int step = s1 - s2;
    if (grp == 0) {          // MACs 64+25 = 89
        diagfs<8>(sb, base + 7*s2,          step, gb + (140 << 4));   // tt=7
        diagfs<5>(sb, base + 4*s2,          step, gb + (30 << 4));    // tt=4
    } else if (grp == 1) {   // 49+36 = 85
        diagfs<7>(sb, base + 6*s2,          step, gb + (91 << 4));    // tt=6
        diagfs<6>(sb, base + 5*s2,          step, gb + (55 << 4));    // tt=5
    } else if (grp == 2) {   // 49+36 = 85
        diagfs<7>(sb, base + s1   + 7*s2,   step, gb + (204 << 4));   // tt=8
        diagfs<6>(sb, base + 2*s1 + 7*s2,   step, gb + (253 << 4));   // tt=9
    } else {                 // 1+4+9+16+25+16+9+4+1 = 85
        diagfs<1>(sb, base,                 step, gb + (0 << 4));     // tt=0
        diagfs<2>(sb, base + s2,            step, gb + (1 << 4));     // tt=1
        diagfs<3>(sb, base + 2*s2,          step, gb + (5 << 4));     // tt=2
        diagfs<4>(sb, base + 3*s2,          step, gb + (14 << 4));    // tt=3
        diagfs<5>(sb, base + 3*s1 + 7*s2,   step, gb + (289 << 4));   // tt=10
        diagfs<4>(sb, base + 4*s1 + 7*s2,   step, gb + (314 << 4));   // tt=11
        diagfs<3>(sb, base + 5*s1 + 7*s2,   step, gb + (330 << 4));   // tt=12
        diagfs<2>(sb, base + 6*s1 + 7*s2,   step, gb + (339 << 4));   // tt=13
        diagfs<1>(sb, base + 7*s1 + 7*s2,   step, gb + (343 << 4));   // tt=14
    }
}

__global__ void __launch_bounds__(256, 2) sim_kernel(float* out) {
    __shared__ float2 st[4096];
    __shared__ ulonglong2 gbuf[2][344];   // double-buffered gate stage (11 KB)
    __shared__ float enc[4][8];
    __shared__ float red[8][4];
    int t = threadIdx.x;
    int b = blockIdx.x;
    unsigned sb = (unsigned)__cvta_generic_to_shared(st);
    unsigned gb0 = (unsigned)__cvta_generic_to_shared(gbuf);

    // stage pass 0 gates
    {
        const ulonglong2* s; int n, ty, pm; pdesc(0, s, n, ty, pm);
        for (int e = t; e < n; e += 256) cpa16(gb0 + (unsigned)(e << 4), s + e);
        asm volatile("cp.async.commit_group;");
    }

    if (t < 32) enc[t >> 3][t & 7] = g_enc0[(b * 4 + (t >> 3)) * 8 + (t & 7)];
    __syncthreads();

    // rank-1 initial state: product of encode column-0 vectors (real)
    #pragma unroll
    for (int k = 0; k < 16; k++) {
        int n = t + (k << 8);
        float v = enc[0][(n >> 9) & 7] * enc[1][(n >> 6) & 7]
                * enc[2][(n >> 3) & 7] * enc[3][n & 7];
        sts64(sb + (unsigned)(phys(n) << 3), pk(v, 0.f));
    }
    asm volatile("cp.async.wait_group 0;" ::: "memory");
    __syncthreads();

    int cur = 0;
    for (int k = 0; k < 80; k++) {
        if (k < 79) {   // stage next pass's gates into the other buffer
            const ulonglong2* s; int n, ty, pm; pdesc(k + 1, s, n, ty, pm);
            unsigned dst = gb0 + (unsigned)((cur ^ 1) * 5504);
            for (int e = t; e < n; e += 256) cpa16(dst + (unsigned)(e << 4), s + e);
        }
        asm volatile("cp.async.commit_group;");
        const ulonglong2* s; int n, ty, pm; pdesc(k, s, n, ty, pm);
        unsigned g = gb0 + (unsigned)(cur * 5504);
        if (ty == 2) apply2s(sb, g, pm, t);
        else         apply1s(sb, g, pm, t);
        asm volatile("cp.async.wait_group 0;" ::: "memory");
        __syncthreads();
        cur ^= 1;
    }

    // expectation values <n_w>
    float ev0 = 0.f, ev1 = 0.f, ev2 = 0.f, ev3 = 0.f;
    #pragma unroll
    for (int k = 0; k < 16; k++) {
        int n = t + (k << 8);
        float re, im;
        upk(lds64(sb + (unsigned)(phys(n) << 3)), re, im);
        float pr = re*re + im*im;
        ev0 += pr * (float)((n >> 9) & 7);
        ev1 += pr * (float)((n >> 6) & 7);
        ev2 += pr * (float)((n >> 3) & 7);
        ev3 += pr * (float)(n & 7);
    }
    #pragma unroll
    for (int off = 16; off; off >>= 1) {
        ev0 += __shfl_xor_sync(0xffffffffu, ev0, off);
        ev1 += __shfl_xor_sync(0xffffffffu, ev1, off);
        ev2 += __shfl_xor_sync(0xffffffffu, ev2, off);
        ev3 += __shfl_xor_sync(0xffffffffu, ev3, off);
    }
    __syncthreads();
    int warp = t >> 5, lane = t & 31;
    if (lane == 0) {
        red[warp][0] = ev0; red[warp][1] = ev1;
        red[warp][2] = ev2; red[warp][3] = ev3;
    }
    __syncthreads();
    if (t < 4) {
        float s = 0.f;
        for (int w = 0; w < 8; w++) s += red[w][t];
        out[b*4 + t] = s;
    }
}

// ---------------- launch ----------------
extern "C" void kernel_launch(void* const* d_in, const int* in_sizes, int n_in,
                              void* d_out, int out_size) {
    const float* x   = (const float*)d_in[0];
    const float* th1 = (const float*)d_in[1];
    const float* ph1 = (const float*)d_in[2];
    const float* th2 = (const float*)d_in[3];
    const float* ph2 = (const float*)d_in[4];
    const float* dr  = (const float*)d_in[5];
    const float* dph = (const float*)d_in[6];
    const float* sr  = (const float*)d_in[7];
    const float* sph = (const float*)d_in[8];
    const float* kr  = (const float*)d_in[9];

    prep_kernel<<<67, 256>>>(x, th1, ph1, th2, ph2, dr, dph, sr, sph, kr);
    sim_kernel<<<NB, 256>>>((float*)d_out);
}

// round 8
// speedup vs baseline: 5.2925x; 1.1317x over previous
#include <cuda_runtime.h>
#include <math.h>

typedef unsigned long long ull;

#define NB 4096

// ---------------- device-global gate storage ----------------
// BS gates packed per photon-number diagonal block:
//   g_bs2[gate*344 + OFF[tt] + r*cnt + rr] = packed folded U[out r][in rr]
// packed entry: .x=(re,re) .y=(im,im) for f32x2 complex MAC
__device__ ulonglong2 g_bs2[48 * 344];
__device__ ulonglong2 g_sq[16 * 64];     // [L][4]: idx j*8+i = U[i][j] packed
__device__ ulonglong2 g_dp[16 * 64];     // [L][4]: Kerr folded on output rows
__device__ float      g_enc0[NB * 4 * 8];// encoding expm column 0 (real)

__constant__ int c_pi[6] = {0,0,0,1,1,2};
__constant__ int c_pj[6] = {1,2,3,2,3,3};
// strides for gate modes and outer modes, per pair p
__constant__ int c_s1[6] = {512,512,512,64,64,8};
__constant__ int c_s2[6] = {64,8,1,8,1,1};
__constant__ int c_sa[6] = {8,64,64,512,512,512};
__constant__ int c_sb[6] = {1,1,8,1,8,64};
// OFF[tt] = cumsum of cnt^2, cnt = 8-|7-tt|
__constant__ int c_off[15] = {0,1,5,14,30,55,91,140,204,253,289,314,330,339,343};

// ---------------- packed helpers ----------------
__device__ __forceinline__ ull pk(float lo, float hi) {
    ull r; asm("mov.b64 %0,{%1,%2};" : "=l"(r) : "f"(lo), "f"(hi)); return r;
}
__device__ __forceinline__ void upk(ull v, float& lo, float& hi) {
    asm("mov.b64 {%0,%1},%2;" : "=f"(lo), "=f"(hi) : "l"(v));
}
__device__ __forceinline__ ull fma2(ull a, ull b, ull c) {
    ull r; asm("fma.rn.f32x2 %0,%1,%2,%3;" : "=l"(r) : "l"(a), "l"(b), "l"(c)); return r;
}
__device__ __forceinline__ ull lds64(unsigned addr) {
    ull r; asm volatile("ld.shared.b64 %0,[%1];" : "=l"(r) : "r"(addr)); return r;
}
__device__ __forceinline__ void sts64(unsigned addr, ull v) {
    asm volatile("st.shared.b64 [%0],%1;" :: "r"(addr), "l"(v));
}
__device__ __forceinline__ ulonglong2 lds128(unsigned addr) {
    ulonglong2 r;
    asm volatile("ld.shared.v2.u64 {%0,%1},[%2];" : "=l"(r.x), "=l"(r.y) : "r"(addr));
    return r;
}
__device__ __forceinline__ void cpa16(unsigned dst, const void* src) {
    asm volatile("cp.async.ca.shared.global [%0],[%1],16;" :: "r"(dst), "l"(src));
}
__device__ __forceinline__ ulonglong2 pks(float re, float im) {
    ulonglong2 r; r.x = pk(re, re); r.y = pk(im, im); return r;
}
// bank-spreading swizzle (bijective within each 16-element block)
__device__ __forceinline__ int phys(int e) {
    return e ^ ((e >> 4) & 15) ^ ((e >> 8) & 15);
}

// ---------------- small expm (scaling-and-squaring Taylor) ----------------
__device__ void matmul_c(const float2* X, const float2* Y, float2* Z, int n, float scale) {
    for (int i = 0; i < n; i++)
        for (int j = 0; j < n; j++) {
            float ar = 0.f, ai = 0.f;
            for (int m = 0; m < n; m++) {
                float2 a = X[i*8+m], b = Y[m*8+j];
                ar += a.x*b.x - a.y*b.y;
                ai += a.x*b.y + a.y*b.x;
            }
            Z[i*8+j] = make_float2(ar*scale, ai*scale);
        }
}

__device__ void expm_c8(const float2* H, float2* E, int n) {
    float norm = 0.f;
    for (int i = 0; i < n; i++) {
        float r = 0.f;
        for (int j = 0; j < n; j++) r += fabsf(H[i*8+j].x) + fabsf(H[i*8+j].y);
        norm = fmaxf(norm, r);
    }
    int s = 0;
    while (norm > 0.5f && s < 30) { norm *= 0.5f; s++; }
    float sc = ldexpf(1.f, -s);
    float2 T[64], P[64], Q[64];
    for (int i = 0; i < n; i++)
        for (int j = 0; j < n; j++) {
            float2 h = H[i*8+j];
            float2 tv = make_float2(h.x*sc, h.y*sc);
            T[i*8+j] = tv; P[i*8+j] = tv; E[i*8+j] = tv;
        }
    for (int i = 0; i < n; i++) E[i*8+i].x += 1.f;
    for (int k = 2; k <= 16; k++) {
        matmul_c(P, T, Q, n, 1.f/(float)k);
        for (int i = 0; i < n; i++)
            for (int j = 0; j < n; j++) {
                P[i*8+j] = Q[i*8+j];
                E[i*8+j].x += Q[i*8+j].x;
                E[i*8+j].y += Q[i*8+j].y;
            }
    }
    for (int it = 0; it < s; it++) {
        matmul_c(E, E, Q, n, 1.f);
        for (int i = 0; i < n; i++)
            for (int j = 0; j < n; j++) E[i*8+j] = Q[i*8+j];
    }
}

__device__ void matmul_r(const float* X, const float* Y, float* Z, int n, float scale) {
    for (int i = 0; i < n; i++)
        for (int j = 0; j < n; j++) {
            float a = 0.f;
            for (int m = 0; m < n; m++) a += X[i*8+m] * Y[m*8+j];
            Z[i*8+j] = a * scale;
        }
}

__device__ void expm_r8(const float* H, float* E, int n) {
    float norm = 0.f;
    for (int i = 0; i < n; i++) {
        float r = 0.f;
        for (int j = 0; j < n; j++) r += fabsf(H[i*8+j]);
        norm = fmaxf(norm, r);
    }
    int s = 0;
    while (norm > 0.5f && s < 30) { norm *= 0.5f; s++; }
    float sc = ldexpf(1.f, -s);
    float T[64], P[64], Q[64];
    for (int i = 0; i < n; i++)
        for (int j = 0; j < n; j++) {
            float tv = H[i*8+j] * sc;
            T[i*8+j] = tv; P[i*8+j] = tv; E[i*8+j] = tv;
        }
    for (int i = 0; i < n; i++) E[i*8+i] += 1.f;
    for (int k = 2; k <= 16; k++) {
        matmul_r(P, T, Q, n, 1.f/(float)k);
        for (int i = 0; i < n; i++)
            for (int j = 0; j < n; j++) { P[i*8+j] = Q[i*8+j]; E[i*8+j] += Q[i*8+j]; }
    }
    for (int it = 0; it < s; it++) {
        matmul_r(E, E, Q, n, 1.f);
        for (int i = 0; i < n; i++)
            for (int j = 0; j < n; j++) E[i*8+j] = Q[i*8+j];
    }
}

// ---------------- combined precompute + encode ----------------
__global__ void prep_kernel(
    const float* x,
    const float* th1, const float* ph1, const float* th2, const float* ph2,
    const float* dr, const float* dph, const float* sr, const float* sph,
    const float* kerr)
{
    if (blockIdx.x < 64) {
        // per-sample encoding displacement: column 0 of real expm
        int tid = blockIdx.x * 256 + threadIdx.x;
        float xv = x[tid];
        float H[64];
        for (int q = 0; q < 64; q++) H[q] = 0.f;
        for (int ii = 1; ii < 8; ii++) {
            float r = xv * sqrtf((float)ii);
            H[ii*8 + ii-1] = r;
            H[(ii-1)*8 + ii] = -r;
        }
        float E[64];
        expm_r8(H, E, 8);
        float* dst = g_enc0 + tid * 8;
        for (int i = 0; i < 8; i++) dst[i] = E[i*8 + 0];
        return;
    }
    int tid = (blockIdx.x - 64) * 256 + threadIdx.x;
    if (tid < 720) {
        // beamsplitter: one photon-number diagonal block per thread
        int g  = tid / 15, tt = tid % 15;
        int l  = g / 12, k = (g / 6) % 2, p = g % 6;
        const float* TH = k ? th2 : th1;
        const float* PH = k ? ph2 : ph1;
        int mi = c_pi[p], mj = c_pj[p];
        float theta = TH[(l*4+mi)*4 + mj];
        float phi   = PH[(l*4+mi)*4 + mj];
        // folded diag phases: input-side rot-pre (first touch per mode), output-side rot-post
        float a1 = 0.f, a2 = 0.f;
        if (p == 0) { a1 = PH[(l*4+0)*4 + 0]; a2 = PH[(l*4+1)*4 + 1]; }
        if (p == 1) { a2 = PH[(l*4+2)*4 + 2]; }
        if (p == 2) { a2 = PH[(l*4+3)*4 + 3]; }
        float b2 = PH[(l*4+mj)*4 + mi];
        int lo = tt > 7 ? tt - 7 : 0;
        int hi = tt < 7 ? tt : 7;
        int n  = hi - lo + 1;
        float2 H[64];
        for (int q = 0; q < 64; q++) H[q] = make_float2(0.f, 0.f);
        float cp = cosf(phi), sp = sinf(phi);
        for (int r = 0; r < n; r++) {
            int j1 = lo + r, j2 = tt - j1;
            if (r >= 1) {
                float mag = theta * sqrtf((float)(j1 * (j2 + 1)));
                H[(r-1)*8 + r] = make_float2(mag*cp, mag*sp);
            }
            if (r <= n - 2) {
                float mag = theta * sqrtf((float)((j1 + 1) * j2));
                H[(r+1)*8 + r] = make_float2(-mag*cp, mag*sp);
            }
        }
        float2 E[64];
        expm_c8(H, E, n);
        ulonglong2* dst = g_bs2 + g * 344 + c_off[tt];
        for (int ir = 0; ir < n; ir++) {
            int i1 = lo + ir, i2 = tt - i1;
            for (int jr = 0; jr < n; jr++) {
                int j1 = lo + jr, j2 = tt - j1;
                float2 v = E[ir*8 + jr];
                float ang = b2 * (float)i2 + a1 * (float)j1 + a2 * (float)j2;
                float ca = cosf(ang), sa = sinf(ang);
                dst[ir*n + jr] = pks(v.x*ca - v.y*sa, v.x*sa + v.y*ca);
            }
        }
    } else if (tid < 736) {
        // squeeze
        int idx = tid - 720;
        float r = sr[idx], p = sph[idx];
        float2 H[64];
        for (int q = 0; q < 64; q++) H[q] = make_float2(0.f, 0.f);
        float cp = cosf(p), sp = sinf(p);
        for (int jj = 2; jj < 8; jj++) {
            float m = 0.5f * r * sqrtf((float)(jj * (jj - 1)));
            H[(jj-2)*8 + jj] = make_float2(m*cp, -m*sp);
            H[jj*8 + jj-2]   = make_float2(-m*cp, -m*sp);
        }
        float2 E[64];
        expm_c8(H, E, 8);
        ulonglong2* dst = g_sq + idx * 64;
        for (int i = 0; i < 8; i++)
            for (int j = 0; j < 8; j++)
                dst[j*8+i] = pks(E[i*8+j].x, E[i*8+j].y);   // idx j*8+i = U[i][j]
    } else if (tid < 752) {
        // layer displacement with Kerr folded on output rows
        int idx = tid - 736;
        float r = dr[idx], p = dph[idx];
        float kp = kerr[idx];
        float amag = r * cosf(p);
        float aph  = r * sinf(p);
        float2 al = make_float2(amag * cosf(aph), amag * sinf(aph));
        float2 H[64];
        for (int q = 0; q < 64; q++) H[q] = make_float2(0.f, 0.f);
        for (int ii = 1; ii < 8; ii++) {
            float rt = sqrtf((float)ii);
            H[ii*8 + ii-1] = make_float2(al.x*rt, al.y*rt);
            H[(ii-1)*8 + ii] = make_float2(-al.x*rt, al.y*rt);
        }
        float2 E[64];
        expm_c8(H, E, 8);
        ulonglong2* dst = g_dp + idx * 64;
        for (int i = 0; i < 8; i++) {
            float ang = kp * (float)(i * i);
            float ca = cosf(ang), sa = sinf(ang);
            for (int j = 0; j < 8; j++) {
                float2 v = E[i*8+j];
                dst[j*8+i] = pks(v.x*ca - v.y*sa, v.x*sa + v.y*ca);
            }
        }
    }
}

// ---------------- pass descriptor ----------------
__device__ __forceinline__ void pdesc(int k, const ulonglong2*& src, int& n, int& ty, int& pm) {
    int l = k / 20, r = k - l*20;
    if (r < 6)       { src = g_bs2 + ((2*l)*6 + r)*344;          n = 344; ty = 2; pm = r; }
    else if (r < 10) { src = g_sq + (l*4 + (r-6))*64;            n = 64;  ty = 1; pm = r-6; }
    else if (r < 16) { src = g_bs2 + ((2*l+1)*6 + (r-10))*344;   n = 344; ty = 2; pm = r-10; }
    else             { src = g_dp + (l*4 + (r-16))*64;           n = 64;  ty = 1; pm = r-16; }
}

// ---------------- main simulation: in-place ownership, gates via smem stream ----------------

// single-mode gate: each thread owns 2 full lines; addresses computed once, reused for store
__device__ __forceinline__ void apply1s(unsigned sb, unsigned gb, int m, int t) {
    int sh = 3 * (3 - m);
    int smask = (1 << sh) - 1;
    int sl0 = 2*t, sl1 = 2*t + 1;
    int base0 = ((sl0 >> sh) << (sh + 3)) | (sl0 & smask);
    int base1 = ((sl1 >> sh) << (sh + 3)) | (sl1 & smask);
    unsigned ad0[8], ad1[8];
    #pragma unroll
    for (int j = 0; j < 8; j++) {
        ad0[j] = sb + (unsigned)(phys(base0 + (j << sh)) << 3);
        ad1[j] = sb + (unsigned)(phys(base1 + (j << sh)) << 3);
    }
    ull aA0[8], aB0[8], aA1[8], aB1[8];
    #pragma unroll
    for (int i = 0; i < 8; i++) { aA0[i]=0ull; aB0[i]=0ull; aA1[i]=0ull; aB1[i]=0ull; }
    #pragma unroll
    for (int j = 0; j < 8; j++) {
        ull v0 = lds64(ad0[j]);
        ull v1 = lds64(ad1[j]);
        #pragma unroll
        for (int i = 0; i < 8; i++) {
            ulonglong2 gg = lds128(gb + (unsigned)((j*8 + i) << 4));
            aA0[i] = fma2(gg.x, v0, aA0[i]); aB0[i] = fma2(gg.y, v0, aB0[i]);
            aA1[i] = fma2(gg.x, v1, aA1[i]); aB1[i] = fma2(gg.y, v1, aB1[i]);
        }
    }
    #pragma unroll
    for (int i = 0; i < 8; i++) {
        float a0, a1, b0, b1;
        upk(aA0[i], a0, a1); upk(aB0[i], b0, b1);
        sts64(ad0[i], pk(a0 - b1, a1 + b0));
        upk(aA1[i], a0, a1); upk(aB1[i], b0, b1);
        sts64(ad1[i], pk(a0 - b1, a1 + b0));
    }
}

// one photon-number diagonal of a 2-mode plane: cnt x cnt in-place matvec
// addresses computed once, reused for the in-place store
template<int CNT>
__device__ __forceinline__ void diagfs(unsigned sb, int e0, int step, unsigned g) {
    unsigned ad[CNT];
    ull aA[CNT], aB[CNT];
    #pragma unroll
    for (int r = 0; r < CNT; r++) {
        ad[r] = sb + (unsigned)(phys(e0 + r*step) << 3);
        aA[r] = 0ull; aB[r] = 0ull;
    }
    #pragma unroll
    for (int rr = 0; rr < CNT; rr++) {
        ull v = lds64(ad[rr]);
        #pragma unroll
        for (int r = 0; r < CNT; r++) {
            ulonglong2 gg = lds128(g + (unsigned)((r*CNT + rr) << 4));
            aA[r] = fma2(gg.x, v, aA[r]);
            aB[r] = fma2(gg.y, v, aB[r]);
        }
    }
    #pragma unroll
    for (int r = 0; r < CNT; r++) {
        float a0, a1, b0, b1;
        upk(aA[r], a0, a1); upk(aB[r], b0, b1);
        sts64(ad[r], pk(a0 - b1, a1 + b0));
    }
}

// two-mode BS gate: warp-per-diag-group (balanced ~300 units each), lane-per-plane
__device__ __forceinline__ void apply2s(unsigned sb, unsigned gb, int p, int t) {
    int s1 = c_s1[p], s2 = c_s2[p], sa = c_sa[p], sbs = c_sb[p];
    int w = t >> 5, lane = t & 31;
    int grp = w & 3;
    int o = ((w >> 2) << 5) | lane;                 // plane 0..63
    int base = (o >> 3) * sa + (o & 7) * sbs;
    int step = s1 - s2;
    if (grp == 0) {          // 192+64+24+10 = 290
        diagfs<8>(sb, base + 7*s2,          step, gb + (140 << 4));   // tt=7
        diagfs<4>(sb, base + 3*s2,          step, gb + (14 << 4));    // tt=3
        diagfs<2>(sb, base + 1*s2,          step, gb + (1 << 4));     // tt=1
        diagfs<1>(sb, base,                 step, gb + (0 << 4));     // tt=0
    } else if (grp == 1) {   // 154+90+42+10 = 296
        diagfs<7>(sb, base + 6*s2,          step, gb + (91 << 4));    // tt=6
        diagfs<5>(sb, base + 4*s2,          step, gb + (30 << 4));    // tt=4
        diagfs<3>(sb, base + 2*s2,          step, gb + (5 << 4));     // tt=2
        diagfs<1>(sb, base + 7*s1 + 7*s2,   step, gb + (343 << 4));   // tt=14
    } else if (grp == 2) {   // 154+90+42+24 = 310
        diagfs<7>(sb, base + s1   + 7*s2,   step, gb + (204 << 4));   // tt=8
        diagfs<5>(sb, base + 3*s1 + 7*s2,   step, gb + (289 << 4));   // tt=10
        diagfs<3>(sb, base + 5*s1 + 7*s2,   step, gb + (330 << 4));   // tt=12
        diagfs<2>(sb, base + 6*s1 + 7*s2,   step, gb + (339 << 4));   // tt=13
    } else {                 // 120+120+64 = 304
        diagfs<6>(sb, base + 5*s2,          step, gb + (55 << 4));    // tt=5
        diagfs<6>(sb, base + 2*s1 + 7*s2,   step, gb + (253 << 4));   // tt=9
        diagfs<4>(sb, base + 4*s1 + 7*s2,   step, gb + (314 << 4));   // tt=11
    }
}

__global__ void __launch_bounds__(256, 2) sim_kernel(float* out) {
    __shared__ float2 st[4096];
    __shared__ ulonglong2 gbuf[2][344];   // double-buffered gate stage (11 KB)
    __shared__ float enc[4][8];
    __shared__ float red[8][4];
    int t = threadIdx.x;
    int b = blockIdx.x;
    unsigned sb = (unsigned)__cvta_generic_to_shared(st);
    unsigned gb0 = (unsigned)__cvta_generic_to_shared(gbuf);

    // stage pass 0 gates
    {
        const ulonglong2* s; int n, ty, pm; pdesc(0, s, n, ty, pm);
        for (int e = t; e < n; e += 256) cpa16(gb0 + (unsigned)(e << 4), s + e);
        asm volatile("cp.async.commit_group;");
    }

    if (t < 32) enc[t >> 3][t & 7] = g_enc0[(b * 4 + (t >> 3)) * 8 + (t & 7)];
    __syncthreads();

    // rank-1 initial state: product of encode column-0 vectors (real)
    #pragma unroll
    for (int k = 0; k < 16; k++) {
        int n = t + (k << 8);
        float v = enc[0][(n >> 9) & 7] * enc[1][(n >> 6) & 7]
                * enc[2][(n >> 3) & 7] * enc[3][n & 7];
        sts64(sb + (unsigned)(phys(n) << 3), pk(v, 0.f));
    }
    asm volatile("cp.async.wait_group 0;" ::: "memory");
    __syncthreads();

    int cur = 0;
    for (int k = 0; k < 80; k++) {
        if (k < 79) {   // stage next pass's gates into the other buffer
            const ulonglong2* s; int n, ty, pm; pdesc(k + 1, s, n, ty, pm);
            unsigned dst = gb0 + (unsigned)((cur ^ 1) * 5504);
            for (int e = t; e < n; e += 256) cpa16(dst + (unsigned)(e << 4), s + e);
        }
        asm volatile("cp.async.commit_group;");
        const ulonglong2* s; int n, ty, pm; pdesc(k, s, n, ty, pm);
        unsigned g = gb0 + (unsigned)(cur * 5504);
        if (ty == 2) apply2s(sb, g, pm, t);
        else         apply1s(sb, g, pm, t);
        asm volatile("cp.async.wait_group 0;" ::: "memory");
        __syncthreads();
        cur ^= 1;
    }

    // expectation values <n_w>
    float ev0 = 0.f, ev1 = 0.f, ev2 = 0.f, ev3 = 0.f;
    #pragma unroll
    for (int k = 0; k < 16; k++) {
        int n = t + (k << 8);
        float re, im;
        upk(lds64(sb + (unsigned)(phys(n) << 3)), re, im);
        float pr = re*re + im*im;
        ev0 += pr * (float)((n >> 9) & 7);
        ev1 += pr * (float)((n >> 6) & 7);
        ev2 += pr * (float)((n >> 3) & 7);
        ev3 += pr * (float)(n & 7);
    }
    #pragma unroll
    for (int off = 16; off; off >>= 1) {
        ev0 += __shfl_xor_sync(0xffffffffu, ev0, off);
        ev1 += __shfl_xor_sync(0xffffffffu, ev1, off);
        ev2 += __shfl_xor_sync(0xffffffffu, ev2, off);
        ev3 += __shfl_xor_sync(0xffffffffu, ev3, off);
    }
    __syncthreads();
    int warp = t >> 5, lane = t & 31;
    if (lane == 0) {
        red[warp][0] = ev0; red[warp][1] = ev1;
        red[warp][2] = ev2; red[warp][3] = ev3;
    }
    __syncthreads();
    if (t < 4) {
        float s = 0.f;
        for (int w = 0; w < 8; w++) s += red[w][t];
        out[b*4 + t] = s;
    }
}

// ---------------- launch ----------------
extern "C" void kernel_launch(void* const* d_in, const int* in_sizes, int n_in,
                              void* d_out, int out_size) {
    const float* x   = (const float*)d_in[0];
    const float* th1 = (const float*)d_in[1];
    const float* ph1 = (const float*)d_in[2];
    const float* th2 = (const float*)d_in[3];
    const float* ph2 = (const float*)d_in[4];
    const float* dr  = (const float*)d_in[5];
    const float* dph = (const float*)d_in[6];
    const float* sr  = (const float*)d_in[7];
    const float* sph = (const float*)d_in[8];
    const float* kr  = (const float*)d_in[9];

    prep_kernel<<<67, 256>>>(x, th1, ph1, th2, ph2, dr, dph, sr, sph, kr);
    sim_kernel<<<NB, 256>>>((float*)d_out);
}

// round 12
// speedup vs baseline: 5.9794x; 1.1298x over previous
#include <cuda_runtime.h>
#include <math.h>

typedef unsigned long long ull;

#define NB 4096
#define ST1OFF 32768   // byte offset of sample-1 state in smem

// ---------------- device-global gate storage ----------------
// BS gates packed per photon-number diagonal block:
//   g_bs2[gate*344 + OFF[tt] + r*cnt + rr] = packed folded U[out r][in rr]
// packed entry: .x=(re,re) .y=(im,im) for f32x2 complex MAC
__device__ ulonglong2 g_bs2[48 * 344];
__device__ ulonglong2 g_sq[16 * 64];     // [L][4]: idx j*8+i = U[i][j] packed
__device__ ulonglong2 g_dp[16 * 64];     // [L][4]: Kerr folded on output rows
__device__ float      g_enc0[NB * 4 * 8];// encoding expm column 0 (real)

__constant__ int c_pi[6] = {0,0,0,1,1,2};
__constant__ int c_pj[6] = {1,2,3,2,3,3};
// strides for gate modes and outer modes, per pair p
__constant__ int c_s1[6] = {512,512,512,64,64,8};
__constant__ int c_s2[6] = {64,8,1,8,1,1};
__constant__ int c_sa[6] = {8,64,64,512,512,512};
__constant__ int c_sb[6] = {1,1,8,1,8,64};
// OFF[tt] = cumsum of cnt^2, cnt = 8-|7-tt|
__constant__ int c_off[15] = {0,1,5,14,30,55,91,140,204,253,289,314,330,339,343};

// ---------------- packed helpers ----------------
__device__ __forceinline__ ull pk(float lo, float hi) {
    ull r; asm("mov.b64 %0,{%1,%2};" : "=l"(r) : "f"(lo), "f"(hi)); return r;
}
__device__ __forceinline__ void upk(ull v, float& lo, float& hi) {
    asm("mov.b64 {%0,%1},%2;" : "=f"(lo), "=f"(hi) : "l"(v));
}
__device__ __forceinline__ ull fma2(ull a, ull b, ull c) {
    ull r; asm("fma.rn.f32x2 %0,%1,%2,%3;" : "=l"(r) : "l"(a), "l"(b), "l"(c)); return r;
}
__device__ __forceinline__ ull lds64(unsigned addr) {
    ull r; asm volatile("ld.shared.b64 %0,[%1];" : "=l"(r) : "r"(addr)); return r;
}
__device__ __forceinline__ ull lds64o(unsigned addr) {   // sample-1 state (imm offset)
    ull r; asm volatile("ld.shared.b64 %0,[%1+32768];" : "=l"(r) : "r"(addr)); return r;
}
__device__ __forceinline__ void sts64(unsigned addr, ull v) {
    asm volatile("st.shared.b64 [%0],%1;" :: "r"(addr), "l"(v));
}
__device__ __forceinline__ void sts64o(unsigned addr, ull v) {
    asm volatile("st.shared.b64 [%0+32768],%1;" :: "r"(addr), "l"(v));
}
__device__ __forceinline__ ulonglong2 lds128(unsigned addr) {
    ulonglong2 r;
    asm volatile("ld.shared.v2.u64 {%0,%1},[%2];" : "=l"(r.x), "=l"(r.y) : "r"(addr));
    return r;
}
__device__ __forceinline__ void cpa16(unsigned dst, const void* src) {
    asm volatile("cp.async.ca.shared.global [%0],[%1],16;" :: "r"(dst), "l"(src));
}
__device__ __forceinline__ ulonglong2 pks(float re, float im) {
    ulonglong2 r; r.x = pk(re, re); r.y = pk(im, im); return r;
}
// bank-spreading swizzle (bijective within each 16-element block)
__device__ __forceinline__ int phys(int e) {
    return e ^ ((e >> 4) & 15) ^ ((e >> 8) & 15);
}

// ---------------- small expm (scaling-and-squaring Taylor) ----------------
__device__ void matmul_c(const float2* X, const float2* Y, float2* Z, int n, float scale) {
    for (int i = 0; i < n; i++)
        for (int j = 0; j < n; j++) {
            float ar = 0.f, ai = 0.f;
            for (int m = 0; m < n; m++) {
                float2 a = X[i*8+m], b = Y[m*8+j];
                ar += a.x*b.x - a.y*b.y;
                ai += a.x*b.y + a.y*b.x;
            }
            Z[i*8+j] = make_float2(ar*scale, ai*scale);
        }
}

__device__ void expm_c8(const float2* H, float2* E, int n) {
    float norm = 0.f;
    for (int i = 0; i < n; i++) {
        float r = 0.f;
        for (int j = 0; j < n; j++) r += fabsf(H[i*8+j].x) + fabsf(H[i*8+j].y);
        norm = fmaxf(norm, r);
    }
    int s = 0;
    while (norm > 0.5f && s < 30) { norm *= 0.5f; s++; }
    float sc = ldexpf(1.f, -s);
    float2 T[64], P[64], Q[64];
    for (int i = 0; i < n; i++)
        for (int j = 0; j < n; j++) {
            float2 h = H[i*8+j];
            float2 tv = make_float2(h.x*sc, h.y*sc);
            T[i*8+j] = tv; P[i*8+j] = tv; E[i*8+j] = tv;
        }
    for (int i = 0; i < n; i++) E[i*8+i].x += 1.f;
    for (int k = 2; k <= 16; k++) {
        matmul_c(P, T, Q, n, 1.f/(float)k);
        for (int i = 0; i < n; i++)
            for (int j = 0; j < n; j++) {
                P[i*8+j] = Q[i*8+j];
                E[i*8+j].x += Q[i*8+j].x;
                E[i*8+j].y += Q[i*8+j].y;
            }
    }
    for (int it = 0; it < s; it++) {
        matmul_c(E, E, Q, n, 1.f);
        for (int i = 0; i < n; i++)
            for (int j = 0; j < n; j++) E[i*8+j] = Q[i*8+j];
    }
}

__device__ void matmul_r(const float* X, const float* Y, float* Z, int n, float scale) {
    for (int i = 0; i < n; i++)
        for (int j = 0; j < n; j++) {
            float a = 0.f;
            for (int m = 0; m < n; m++) a += X[i*8+m] * Y[m*8+j];
            Z[i*8+j] = a * scale;
        }
}

__device__ void expm_r8(const float* H, float* E, int n) {
    float norm = 0.f;
    for (int i = 0; i < n; i++) {
        float r = 0.f;
        for (int j = 0; j < n; j++) r += fabsf(H[i*8+j]);
        norm = fmaxf(norm, r);
    }
    int s = 0;
    while (norm > 0.5f && s < 30) { norm *= 0.5f; s++; }
    float sc = ldexpf(1.f, -s);
    float T[64], P[64], Q[64];
    for (int i = 0; i < n; i++)
        for (int j = 0; j < n; j++) {
            float tv = H[i*8+j] * sc;
            T[i*8+j] = tv; P[i*8+j] = tv; E[i*8+j] = tv;
        }
    for (int i = 0; i < n; i++) E[i*8+i] += 1.f;
    for (int k = 2; k <= 16; k++) {
        matmul_r(P, T, Q, n, 1.f/(float)k);
        for (int i = 0; i < n; i++)
            for (int j = 0; j < n; j++) { P[i*8+j] = Q[i*8+j]; E[i*8+j] += Q[i*8+j]; }
    }
    for (int it = 0; it < s; it++) {
        matmul_r(E, E, Q, n, 1.f);
        for (int i = 0; i < n; i++)
            for (int j = 0; j < n; j++) E[i*8+j] = Q[i*8+j];
    }
}

// ---------------- combined precompute + encode ----------------
__global__ void prep_kernel(
    const float* x,
    const float* th1, const float* ph1, const float* th2, const float* ph2,
    const float* dr, const float* dph, const float* sr, const float* sph,
    const float* kerr)
{
    if (blockIdx.x < 64) {
        // per-sample encoding displacement: column 0 of real expm
        int tid = blockIdx.x * 256 + threadIdx.x;
        float xv = x[tid];
        float H[64];
        for (int q = 0; q < 64; q++) H[q] = 0.f;
        for (int ii = 1; ii < 8; ii++) {
            float r = xv * sqrtf((float)ii);
            H[ii*8 + ii-1] = r;
            H[(ii-1)*8 + ii] = -r;
        }
        float E[64];
        expm_r8(H, E, 8);
        float* dst = g_enc0 + tid * 8;
        for (int i = 0; i < 8; i++) dst[i] = E[i*8 + 0];
        return;
    }
    int tid = (blockIdx.x - 64) * 256 + threadIdx.x;
    if (tid < 720) {
        // beamsplitter: one photon-number diagonal block per thread
        int g  = tid / 15, tt = tid % 15;
        int l  = g / 12, k = (g / 6) % 2, p = g % 6;
        const float* TH = k ? th2 : th1;
        const float* PH = k ? ph2 : ph1;
        int mi = c_pi[p], mj = c_pj[p];
        float theta = TH[(l*4+mi)*4 + mj];
        float phi   = PH[(l*4+mi)*4 + mj];
        // folded diag phases: input-side rot-pre (first touch per mode), output-side rot-post
        float a1 = 0.f, a2 = 0.f;
        if (p == 0) { a1 = PH[(l*4+0)*4 + 0]; a2 = PH[(l*4+1)*4 + 1]; }
        if (p == 1) { a2 = PH[(l*4+2)*4 + 2]; }
        if (p == 2) { a2 = PH[(l*4+3)*4 + 3]; }
        float b2 = PH[(l*4+mj)*4 + mi];
        int lo = tt > 7 ? tt - 7 : 0;
        int hi = tt < 7 ? tt : 7;
        int n  = hi - lo + 1;
        float2 H[64];
        for (int q = 0; q < 64; q++) H[q] = make_float2(0.f, 0.f);
        float cp = cosf(phi), sp = sinf(phi);
        for (int r = 0; r < n; r++) {
            int j1 = lo + r, j2 = tt - j1;
            if (r >= 1) {
                float mag = theta * sqrtf((float)(j1 * (j2 + 1)));
                H[(r-1)*8 + r] = make_float2(mag*cp, mag*sp);
            }
            if (r <= n - 2) {
                float mag = theta * sqrtf((float)((j1 + 1) * j2));
                H[(r+1)*8 + r] = make_float2(-mag*cp, mag*sp);
            }
        }
        float2 E[64];
        expm_c8(H, E, n);
        ulonglong2* dst = g_bs2 + g * 344 + c_off[tt];
        for (int ir = 0; ir < n; ir++) {
            int i1 = lo + ir, i2 = tt - i1;
            for (int jr = 0; jr < n; jr++) {
                int j1 = lo + jr, j2 = tt - j1;
                float2 v = E[ir*8 + jr];
                float ang = b2 * (float)i2 + a1 * (float)j1 + a2 * (float)j2;
                float ca = cosf(ang), sa = sinf(ang);
                dst[ir*n + jr] = pks(v.x*ca - v.y*sa, v.x*sa + v.y*ca);
            }
        }
    } else if (tid < 736) {
        // squeeze
        int idx = tid - 720;
        float r = sr[idx], p = sph[idx];
        float2 H[64];
        for (int q = 0; q < 64; q++) H[q] = make_float2(0.f, 0.f);
        float cp = cosf(p), sp = sinf(p);
        for (int jj = 2; jj < 8; jj++) {
            float m = 0.5f * r * sqrtf((float)(jj * (jj - 1)));
            H[(jj-2)*8 + jj] = make_float2(m*cp, -m*sp);
            H[jj*8 + jj-2]   = make_float2(-m*cp, -m*sp);
        }
        float2 E[64];
        expm_c8(H, E, 8);
        ulonglong2* dst = g_sq + idx * 64;
        for (int i = 0; i < 8; i++)
            for (int j = 0; j < 8; j++)
                dst[j*8+i] = pks(E[i*8+j].x, E[i*8+j].y);   // idx j*8+i = U[i][j]
    } else if (tid < 752) {
        // layer displacement with Kerr folded on output rows
        int idx = tid - 736;
        float r = dr[idx], p = dph[idx];
        float kp = kerr[idx];
        float amag = r * cosf(p);
        float aph  = r * sinf(p);
        float2 al = make_float2(amag * cosf(aph), amag * sinf(aph));
        float2 H[64];
        for (int q = 0; q < 64; q++) H[q] = make_float2(0.f, 0.f);
        for (int ii = 1; ii < 8; ii++) {
            float rt = sqrtf((float)ii);
            H[ii*8 + ii-1] = make_float2(al.x*rt, al.y*rt);
            H[(ii-1)*8 + ii] = make_float2(-al.x*rt, al.y*rt);
        }
        float2 E[64];
        expm_c8(H, E, 8);
        ulonglong2* dst = g_dp + idx * 64;
        for (int i = 0; i < 8; i++) {
            float ang = kp * (float)(i * i);
            float ca = cosf(ang), sa = sinf(ang);
            for (int j = 0; j < 8; j++) {
                float2 v = E[i*8+j];
                dst[j*8+i] = pks(v.x*ca - v.y*sa, v.x*sa + v.y*ca);
            }
        }
    }
}

// ---------------- pass descriptor ----------------
__device__ __forceinline__ void pdesc(int k, const ulonglong2*& src, int& n, int& ty, int& pm) {
    int l = k / 20, r = k - l*20;
    if (r < 6)       { src = g_bs2 + ((2*l)*6 + r)*344;          n = 344; ty = 2; pm = r; }
    else if (r < 10) { src = g_sq + (l*4 + (r-6))*64;            n = 64;  ty = 1; pm = r-6; }
    else if (r < 16) { src = g_bs2 + ((2*l+1)*6 + (r-10))*344;   n = 344; ty = 2; pm = r-10; }
    else             { src = g_dp + (l*4 + (r-16))*64;           n = 64;  ty = 1; pm = r-16; }
}

// ---------------- main simulation: 2 samples/CTA, in-place, smem gate stream ----------------

// single-mode gate: per q-iteration one line of BOTH states share each gate load
__device__ __forceinline__ void apply1s(unsigned sb, unsigned gb, int m, int t) {
    int sh = 3 * (3 - m);
    int smask = (1 << sh) - 1;
    #pragma unroll 1
    for (int q = 0; q < 2; q++) {
        int sl = 2*t + q;
        int base = ((sl >> sh) << (sh + 3)) | (sl & smask);
        unsigned ad[8];
        #pragma unroll
        for (int j = 0; j < 8; j++)
            ad[j] = sb + (unsigned)(phys(base + (j << sh)) << 3);
        ull aA[8], aB[8], cA[8], cB[8];
        #pragma unroll
        for (int i = 0; i < 8; i++) { aA[i]=0ull; aB[i]=0ull; cA[i]=0ull; cB[i]=0ull; }
        #pragma unroll
        for (int j = 0; j < 8; j++) {
            ull v0 = lds64(ad[j]);
            ull v1 = lds64o(ad[j]);
            #pragma unroll
            for (int i = 0; i < 8; i++) {
                ulonglong2 gg = lds128(gb + (unsigned)((j*8 + i) << 4));
                aA[i] = fma2(gg.x, v0, aA[i]); aB[i] = fma2(gg.y, v0, aB[i]);
                cA[i] = fma2(gg.x, v1, cA[i]); cB[i] = fma2(gg.y, v1, cB[i]);
            }
        }
        #pragma unroll
        for (int i = 0; i < 8; i++) {
            float a0, a1, b0, b1;
            upk(aA[i], a0, a1); upk(aB[i], b0, b1);
            sts64(ad[i], pk(a0 - b1, a1 + b0));
            upk(cA[i], a0, a1); upk(cB[i], b0, b1);
            sts64o(ad[i], pk(a0 - b1, a1 + b0));
        }
    }
}

// one photon-number diagonal of a 2-mode plane, applied to BOTH states
template<int CNT>
__device__ __forceinline__ void diagfs(unsigned sb, int e0, int step, unsigned g) {
    unsigned ad[CNT];
    ull aA[CNT], aB[CNT], cA[CNT], cB[CNT];
    #pragma unroll
    for (int r = 0; r < CNT; r++) {
        ad[r] = sb + (unsigned)(phys(e0 + r*step) << 3);
        aA[r] = 0ull; aB[r] = 0ull; cA[r] = 0ull; cB[r] = 0ull;
    }
    #pragma unroll
    for (int rr = 0; rr < CNT; rr++) {
        ull v0 = lds64(ad[rr]);
        ull v1 = lds64o(ad[rr]);
        #pragma unroll
        for (int r = 0; r < CNT; r++) {
            ulonglong2 gg = lds128(g + (unsigned)((r*CNT + rr) << 4));
            aA[r] = fma2(gg.x, v0, aA[r]);
            aB[r] = fma2(gg.y, v0, aB[r]);
            cA[r] = fma2(gg.x, v1, cA[r]);
            cB[r] = fma2(gg.y, v1, cB[r]);
        }
    }
    #pragma unroll
    for (int r = 0; r < CNT; r++) {
        float a0, a1, b0, b1;
        upk(aA[r], a0, a1); upk(aB[r], b0, b1);
        sts64(ad[r], pk(a0 - b1, a1 + b0));
        upk(cA[r], a0, a1); upk(cB[r], b0, b1);
        sts64o(ad[r], pk(a0 - b1, a1 + b0));
    }
}

// two-mode BS gate: warp-per-diag-group (balanced), lane-per-plane, both states
__device__ __forceinline__ void apply2s(unsigned sb, unsigned gb, int p, int t) {
    int s1 = c_s1[p], s2 = c_s2[p], sa = c_sa[p], sbs = c_sb[p];
    int w = t >> 5, lane = t & 31;
    int grp = w & 3;
    int o = ((w >> 2) << 5) | lane;                 // plane 0..63
    int base = (o >> 3) * sa + (o & 7) * sbs;
    int step = s1 - s2;
    if (grp == 0) {          // 192+64+24+10 = 290
        diagfs<8>(sb, base + 7*s2,          step, gb + (140 << 4));   // tt=7
        diagfs<4>(sb, base + 3*s2,          step, gb + (14 << 4));    // tt=3
        diagfs<2>(sb, base + 1*s2,          step, gb + (1 << 4));     // tt=1
        diagfs<1>(sb, base,                 step, gb + (0 << 4));     // tt=0
    } else if (grp == 1) {   // 154+90+42+10 = 296
        diagfs<7>(sb, base + 6*s2,          step, gb + (91 << 4));    // tt=6
        diagfs<5>(sb, base + 4*s2,          step, gb + (30 << 4));    // tt=4
        diagfs<3>(sb, base + 2*s2,          step, gb + (5 << 4));     // tt=2
        diagfs<1>(sb, base + 7*s1 + 7*s2,   step, gb + (343 << 4));   // tt=14
    } else if (grp == 2) {   // 154+90+42+24 = 310
        diagfs<7>(sb, base + s1   + 7*s2,   step, gb + (204 << 4));   // tt=8
        diagfs<5>(sb, base + 3*s1 + 7*s2,   step, gb + (289 << 4));   // tt=10
        diagfs<3>(sb, base + 5*s1 + 7*s2,   step, gb + (330 << 4));   // tt=12
        diagfs<2>(sb, base + 6*s1 + 7*s2,   step, gb + (339 << 4));   // tt=13
    } else {                 // 120+120+64 = 304
        diagfs<6>(sb, base + 5*s2,          step, gb + (55 << 4));    // tt=5
        diagfs<6>(sb, base + 2*s1 + 7*s2,   step, gb + (253 << 4));   // tt=9
        diagfs<4>(sb, base + 4*s1 + 7*s2,   step, gb + (314 << 4));   // tt=11
    }
}

extern __shared__ float2 dynsmem[];   // [0,64KB): two states; [64KB,+11KB): gate buffers

__global__ void __launch_bounds__(256, 2) sim_kernel(float* out) {
    __shared__ float enc[2][4][8];
    __shared__ float red[2][8][4];
    int t = threadIdx.x;
    int b = blockIdx.x;      // handles samples 2b, 2b+1
    unsigned sb  = (unsigned)__cvta_generic_to_shared(dynsmem);
    unsigned gb0 = sb + 65536u;

    // stage pass 0 gates
    {
        const ulonglong2* s; int n, ty, pm; pdesc(0, s, n, ty, pm);
        for (int e = t; e < n; e += 256) cpa16(gb0 + (unsigned)(e << 4), s + e);
        asm volatile("cp.async.commit_group;");
    }

    if (t < 64) enc[t >> 5][(t >> 3) & 3][t & 7] = g_enc0[(b*8 + (t >> 3))*8 + (t & 7)];
    __syncthreads();

    // rank-1 initial states
    #pragma unroll
    for (int k = 0; k < 16; k++) {
        int n = t + (k << 8);
        int i0 = (n >> 9) & 7, i1 = (n >> 6) & 7, i2 = (n >> 3) & 7, i3 = n & 7;
        float v0 = enc[0][0][i0] * enc[0][1][i1] * enc[0][2][i2] * enc[0][3][i3];
        float v1 = enc[1][0][i0] * enc[1][1][i1] * enc[1][2][i2] * enc[1][3][i3];
        unsigned a = sb + (unsigned)(phys(n) << 3);
        sts64(a, pk(v0, 0.f));
        sts64o(a, pk(v1, 0.f));
    }
    asm volatile("cp.async.wait_group 0;" ::: "memory");
    __syncthreads();

    int cur = 0;
    for (int k = 0; k < 80; k++) {
        if (k < 79) {   // stage next pass's gates into the other buffer
            const ulonglong2* s; int n, ty, pm; pdesc(k + 1, s, n, ty, pm);
            unsigned dst = gb0 + (unsigned)((cur ^ 1) * 5504);
            for (int e = t; e < n; e += 256) cpa16(dst + (unsigned)(e << 4), s + e);
        }
        asm volatile("cp.async.commit_group;");
        const ulonglong2* s; int n, ty, pm; pdesc(k, s, n, ty, pm);
        unsigned g = gb0 + (unsigned)(cur * 5504);
        if (ty == 2) apply2s(sb, g, pm, t);
        else         apply1s(sb, g, pm, t);
        asm volatile("cp.async.wait_group 0;" ::: "memory");
        __syncthreads();
        cur ^= 1;
    }

    // expectation values <n_w> for both samples
    int warp = t >> 5, lane = t & 31;
    #pragma unroll 1
    for (int q = 0; q < 2; q++) {
        float ev0 = 0.f, ev1 = 0.f, ev2 = 0.f, ev3 = 0.f;
        #pragma unroll
        for (int k = 0; k < 16; k++) {
            int n = t + (k << 8);
            unsigned a = sb + (unsigned)(phys(n) << 3);
            float re, im;
            if (q == 0) { upk(lds64(a), re, im); } else { upk(lds64o(a), re, im); }
            float pr = re*re + im*im;
            ev0 += pr * (float)((n >> 9) & 7);
            ev1 += pr * (float)((n >> 6) & 7);
            ev2 += pr * (float)((n >> 3) & 7);
            ev3 += pr * (float)(n & 7);
        }
        #pragma unroll
        for (int off = 16; off; off >>= 1) {
            ev0 += __shfl_xor_sync(0xffffffffu, ev0, off);
            ev1 += __shfl_xor_sync(0xffffffffu, ev1, off);
            ev2 += __shfl_xor_sync(0xffffffffu, ev2, off);
            ev3 += __shfl_xor_sync(0xffffffffu, ev3, off);
        }
        if (lane == 0) {
            red[q][warp][0] = ev0; red[q][warp][1] = ev1;
            red[q][warp][2] = ev2; red[q][warp][3] = ev3;
        }
    }
    __syncthreads();
    if (t < 8) {
        int q = t >> 2, m = t & 3;
        float s = 0.f;
        for (int w = 0; w < 8; w++) s += red[q][w][m];
        out[(b*2 + q)*4 + m] = s;
    }
}

// ---------------- launch ----------------
extern "C" void kernel_launch(void* const* d_in, const int* in_sizes, int n_in,
                              void* d_out, int out_size) {
    const float* x   = (const float*)d_in[0];
    const float* th1 = (const float*)d_in[1];
    const float* ph1 = (const float*)d_in[2];
    const float* th2 = (const float*)d_in[3];
    const float* ph2 = (const float*)d_in[4];
    const float* dr  = (const float*)d_in[5];
    const float* dph = (const float*)d_in[6];
    const float* sr  = (const float*)d_in[7];
    const float* sph = (const float*)d_in[8];
    const float* kr  = (const float*)d_in[9];

    static int smem_set = 0;
    if (!smem_set) {
        cudaFuncSetAttribute(sim_kernel, cudaFuncAttributeMaxDynamicSharedMemorySize,
                             65536 + 11008);
        smem_set = 1;
    }

    prep_kernel<<<67, 256>>>(x, th1, ph1, th2, ph2, dr, dph, sr, sph, kr);
    sim_kernel<<<NB/2, 256, 65536 + 11008>>>((float*)d_out);
}